// round 3
// baseline (speedup 1.0000x reference)
#include <cuda_runtime.h>
#include <math.h>

#define BATCH 2048
#define HGT 7
#define WID 24
#define PIX 168            // 7*24
#define SROW 26            // padded row width (24 + halo)
#define SPLANE (9*SROW)    // padded plane per channel (7+halo rows)

#define C0IN 2
#define HC0 32
#define HC1 64

// ---------------- scratch (static device allocations; no cudaMalloc) ----------------
__device__ float g_gx0[(size_t)BATCH * 128 * PIX];        // conv(input,Wx0)+bx0, time-invariant
__device__ float g_h0[2][(size_t)BATCH * HC0 * PIX];      // ping-pong hidden, layer 0
__device__ float g_c0[(size_t)BATCH * HC0 * PIX];         // cell state layer 0 (in-place)
__device__ float g_h1[2][(size_t)BATCH * HC1 * PIX];      // ping-pong hidden, layer 1
__device__ float g_c1[(size_t)BATCH * HC1 * PIX];         // cell state layer 1 (in-place)
__device__ float g_fcwT[10752 * 64];                      // fc1_w transposed, o-paired layout

// ---------------- init ----------------
__global__ void k_zero() {
    size_t stride = (size_t)gridDim.x * blockDim.x;
    size_t gid = (size_t)blockIdx.x * blockDim.x + threadIdx.x;
    const size_t N0 = (size_t)BATCH * HC0 * PIX;
    const size_t N1 = (size_t)BATCH * HC1 * PIX;
    for (size_t i = gid; i < N0; i += stride) { g_h0[0][i] = 0.f; g_c0[i] = 0.f; }
    for (size_t i = gid; i < N1; i += stride) { g_h1[0][i] = 0.f; g_c1[i] = 0.f; }
}

// ---------------- gx0 = conv(input, Wx0) + bx0 (once) ----------------
__global__ void k_gx0(const float* __restrict__ input, const float* __restrict__ Wx0,
                      const float* __restrict__ bx0) {
    __shared__ float sin_[C0IN * SPLANE];
    int b = blockIdx.x, tid = threadIdx.x;
    for (int i = tid; i < C0IN * SPLANE; i += blockDim.x) sin_[i] = 0.f;
    __syncthreads();
    for (int u = tid; u < C0IN * PIX; u += blockDim.x) {
        int ic = u / PIX, pix = u % PIX, y = pix / WID, x = pix % WID;
        sin_[ic * SPLANE + (y + 1) * SROW + (x + 1)] = input[(size_t)b * C0IN * PIX + u];
    }
    __syncthreads();
    for (int u = tid; u < 128 * PIX; u += blockDim.x) {
        int oc = u / PIX, pix = u % PIX, y = pix / WID, x = pix % WID;
        float acc = bx0[oc];
#pragma unroll
        for (int ic = 0; ic < C0IN; ic++)
#pragma unroll
            for (int ky = 0; ky < 3; ky++)
#pragma unroll
                for (int kx = 0; kx < 3; kx++)
                    acc += sin_[ic * SPLANE + (y + ky) * SROW + (x + kx)] *
                           __ldg(&Wx0[oc * 18 + ic * 9 + ky * 3 + kx]);
        g_gx0[(size_t)b * 128 * PIX + u] = acc;
    }
}

// ---------------- conv accumulation core ----------------
// Accumulates the 4 gate pre-activations for hidden-channel hc over 8 consecutive
// pixels (one row segment), reading the zero-padded plane from SMEM.
// W layout: [4*HCOUT, C, 3, 3]; gate g for channel hc is output channel g*HCOUT+hc.
template <int C, int GSTRIDE>
__device__ __forceinline__ void conv_accum(const float* __restrict__ W, const float* sh,
                                           int hc, int row, int xbase, float (&acc)[4][8]) {
    const float* wb = W + hc * C * 9;
#pragma unroll 1
    for (int ic = 0; ic < C; ic++) {
#pragma unroll
        for (int ky = 0; ky < 3; ky++) {
            const float* srow = sh + ic * SPLANE + (row + ky) * SROW + xbase;
            float v[10];
#pragma unroll
            for (int q = 0; q < 10; q++) v[q] = srow[q];
            const float* wp = wb + ic * 9 + ky * 3;
            float wr[4][3];
#pragma unroll
            for (int g = 0; g < 4; g++)
#pragma unroll
                for (int kx = 0; kx < 3; kx++)
                    wr[g][kx] = __ldg(wp + (size_t)g * GSTRIDE + kx);
#pragma unroll
            for (int kx = 0; kx < 3; kx++)
#pragma unroll
                for (int g = 0; g < 4; g++)
#pragma unroll
                    for (int p = 0; p < 8; p++)
                        acc[g][p] = fmaf(v[p + kx], wr[g][kx], acc[g][p]);
        }
    }
}

__device__ __forceinline__ float sigf(float x) { return 1.f / (1.f + expf(-x)); }

// ---------------- layer-0 cell step ----------------
__global__ void __launch_bounds__(224, 2)
k_cell0(const float* __restrict__ Wh0, const float* __restrict__ Wc0, int s) {
    extern __shared__ float sh[];  // HC0 * SPLANE
    int b = blockIdx.x, tid = threadIdx.x;
    int src = s & 1, dst = src ^ 1;
    const float* h0s = g_h0[src] + (size_t)b * HC0 * PIX;
    for (int i = tid; i < HC0 * SPLANE; i += blockDim.x) sh[i] = 0.f;
    __syncthreads();
    for (int u = tid; u < HC0 * PIX; u += blockDim.x) {
        int ic = u / PIX, pix = u % PIX, y = pix / WID, x = pix % WID;
        sh[ic * SPLANE + (y + 1) * SROW + x + 1] = h0s[u];
    }
    __syncthreads();
    const float* gx = g_gx0 + (size_t)b * 128 * PIX;
#pragma unroll 1
    for (int it = 0; it < 3; it++) {           // 32*21 = 672 tasks, 224 threads
        int task = tid + it * 224;
        int hc = task / 21, g8 = task % 21;
        int row = g8 / 3, xbase = (g8 % 3) * 8;
        int pixbase = row * WID + xbase;
        float acc[4][8];
#pragma unroll
        for (int g = 0; g < 4; g++)
#pragma unroll
            for (int p = 0; p < 8; p++)
                acc[g][p] = gx[(g * HC0 + hc) * PIX + pixbase + p];
        conv_accum<HC0, HC0 * HC0 * 9>(Wh0, sh, hc, row, xbase, acc);

        float* cptr = g_c0 + (size_t)b * HC0 * PIX + hc * PIX + pixbase;
        float* hptr = g_h0[dst] + (size_t)b * HC0 * PIX + hc * PIX + pixbase;
        const float* wc = Wc0 + hc * PIX + pixbase;
#pragma unroll
        for (int p = 0; p < 8; p++) {
            float c = cptr[p];
            float ci = sigf(acc[0][p] + c * wc[p]);
            float cf = sigf(acc[1][p] + c * wc[HC0 * PIX + p]);
            float cc = cf * c + ci * tanhf(acc[2][p]);
            float co = sigf(acc[3][p] + cc * wc[2 * HC0 * PIX + p]);
            cptr[p] = cc;
            hptr[p] = co * tanhf(cc);
        }
    }
}

// ---------------- layer-1 cell step ----------------
__global__ void __launch_bounds__(224, 2)
k_cell1(const float* __restrict__ Wx1, const float* __restrict__ bx1,
        const float* __restrict__ Wh1, const float* __restrict__ Wc1, int s) {
    extern __shared__ float sh[];  // (HC0+HC1) * SPLANE
    int b = blockIdx.x, tid = threadIdx.x;
    int src = s & 1, dst = src ^ 1;
    const float* h0n = g_h0[dst] + (size_t)b * HC0 * PIX;  // freshly written by k_cell0
    const float* h1s = g_h1[src] + (size_t)b * HC1 * PIX;
    float* sh0 = sh;
    float* sh1 = sh + HC0 * SPLANE;
    for (int i = tid; i < (HC0 + HC1) * SPLANE; i += blockDim.x) sh[i] = 0.f;
    __syncthreads();
    for (int u = tid; u < HC0 * PIX; u += blockDim.x) {
        int ic = u / PIX, pix = u % PIX, y = pix / WID, x = pix % WID;
        sh0[ic * SPLANE + (y + 1) * SROW + x + 1] = h0n[u];
    }
    for (int u = tid; u < HC1 * PIX; u += blockDim.x) {
        int ic = u / PIX, pix = u % PIX, y = pix / WID, x = pix % WID;
        sh1[ic * SPLANE + (y + 1) * SROW + x + 1] = h1s[u];
    }
    __syncthreads();
#pragma unroll 1
    for (int it = 0; it < 6; it++) {           // 64*21 = 1344 tasks, 224 threads
        int task = tid + it * 224;
        int hc = task / 21, g8 = task % 21;
        int row = g8 / 3, xbase = (g8 % 3) * 8;
        int pixbase = row * WID + xbase;
        float acc[4][8];
#pragma unroll
        for (int g = 0; g < 4; g++) {
            float bv = bx1[g * HC1 + hc];
#pragma unroll
            for (int p = 0; p < 8; p++) acc[g][p] = bv;
        }
        conv_accum<HC0, HC1 * HC0 * 9>(Wx1, sh0, hc, row, xbase, acc);
        conv_accum<HC1, HC1 * HC1 * 9>(Wh1, sh1, hc, row, xbase, acc);

        float* cptr = g_c1 + (size_t)b * HC1 * PIX + hc * PIX + pixbase;
        float* hptr = g_h1[dst] + (size_t)b * HC1 * PIX + hc * PIX + pixbase;
        const float* wc = Wc1 + hc * PIX + pixbase;
#pragma unroll
        for (int p = 0; p < 8; p++) {
            float c = cptr[p];
            float ci = sigf(acc[0][p] + c * wc[p]);
            float cf = sigf(acc[1][p] + c * wc[HC1 * PIX + p]);
            float cc = cf * c + ci * tanhf(acc[2][p]);
            float co = sigf(acc[3][p] + cc * wc[2 * HC1 * PIX + p]);
            cptr[p] = cc;
            hptr[p] = co * tanhf(cc);
        }
    }
}

// ---------------- fc1 weight transpose (coalesced fc consumption) ----------------
// g_fcwT[k*64 + (o&31)*2 + (o>>5)] = fc1_w[o*10752 + k]
__global__ void k_wt(const float* __restrict__ fc1_w) {
    int idx = blockIdx.x * blockDim.x + threadIdx.x;
    if (idx >= 10752 * 64) return;
    int k = idx / 64, o = idx % 64;
    g_fcwT[k * 64 + (o & 31) * 2 + (o >> 5)] = fc1_w[(size_t)o * 10752 + k];
}

// ---------------- fc1 head: out[:, 0:64] = relu(h1_final @ fc1_w^T + b) ----------------
__global__ void k_fc(const float* __restrict__ fc1_b, float* __restrict__ out) {
    __shared__ float shh[8 * 1344];
    int tid = threadIdx.x;
    int b0 = blockIdx.x * 8;
    int it = tid >> 5, o = tid & 31;   // 8 items x 32 output-pairs
    float acc0 = 0.f, acc1 = 0.f;
    const float* h1f = g_h1[1];        // after 7 steps final h1 lives in buffer 1
#pragma unroll 1
    for (int cb = 0; cb < 8; cb++) {
        __syncthreads();
        for (int u = tid; u < 8 * 1344; u += 256) {
            int i2 = u / 1344, kk = u % 1344;
            shh[u] = h1f[(size_t)(b0 + i2) * 10752 + cb * 1344 + kk];
        }
        __syncthreads();
        const float* wp = g_fcwT + (size_t)cb * 1344 * 64 + o * 2;
        const float* hp = shh + it * 1344;
#pragma unroll 4
        for (int kk = 0; kk < 1344; kk++) {
            float hv = hp[kk];
            float2 w2 = __ldg((const float2*)(wp + (size_t)kk * 64));
            acc0 = fmaf(hv, w2.x, acc0);
            acc1 = fmaf(hv, w2.y, acc1);
        }
    }
    out[(size_t)(b0 + it) * 128 + o] = fmaxf(acc0 + fc1_b[o], 0.f);
    out[(size_t)(b0 + it) * 128 + o + 32] = fmaxf(acc1 + fc1_b[o + 32], 0.f);
}

// ---------------- exfc head: out[:, 64:128] = relu(x_ex @ exfc_w^T + b) ----------------
__global__ void k_exfc(const float* __restrict__ x_ex, const float* __restrict__ w,
                       const float* __restrict__ bias, float* __restrict__ out) {
    int idx = blockIdx.x * blockDim.x + threadIdx.x;
    if (idx >= BATCH * 64) return;
    int b = idx >> 6, o = idx & 63;
    float acc = bias[o];
#pragma unroll
    for (int k = 0; k < 24; k++) acc += x_ex[b * 24 + k] * __ldg(&w[o * 24 + k]);
    out[(size_t)b * 128 + 64 + o] = fmaxf(acc, 0.f);
}

// ---------------- launch ----------------
extern "C" void kernel_launch(void* const* d_in, const int* in_sizes, int n_in,
                              void* d_out, int out_size) {
    const float* input  = (const float*)d_in[0];
    const float* x_ex   = (const float*)d_in[1];
    const float* Wx0    = (const float*)d_in[2];
    const float* bx0    = (const float*)d_in[3];
    const float* Wh0    = (const float*)d_in[4];
    const float* Wc0    = (const float*)d_in[5];
    const float* Wx1    = (const float*)d_in[6];
    const float* bx1    = (const float*)d_in[7];
    const float* Wh1    = (const float*)d_in[8];
    const float* Wc1    = (const float*)d_in[9];
    const float* fc1_w  = (const float*)d_in[10];
    const float* fc1_b  = (const float*)d_in[11];
    const float* exfc_w = (const float*)d_in[12];
    const float* exfc_b = (const float*)d_in[13];
    float* out = (float*)d_out;

    (void)in_sizes; (void)n_in; (void)out_size;

    // cell1 needs ~88KB dynamic SMEM (attr set is immediate / not captured; idempotent)
    cudaFuncSetAttribute(k_cell1, cudaFuncAttributeMaxDynamicSharedMemorySize,
                         (HC0 + HC1) * SPLANE * (int)sizeof(float));

    k_zero<<<4096, 256>>>();
    k_gx0<<<BATCH, 256>>>(input, Wx0, bx0);
    k_wt<<<(10752 * 64 + 255) / 256, 256>>>(fc1_w);

    for (int s = 0; s < 7; s++) {
        k_cell0<<<BATCH, 224, HC0 * SPLANE * (int)sizeof(float)>>>(Wh0, Wc0, s);
        k_cell1<<<BATCH, 224, (HC0 + HC1) * SPLANE * (int)sizeof(float)>>>(Wx1, bx1, Wh1, Wc1, s);
    }

    k_fc<<<BATCH / 8, 256>>>(fc1_b, out);
    k_exfc<<<(BATCH * 64 + 255) / 256, 256>>>(x_ex, exfc_w, exfc_b, out);
}

// round 4
// speedup vs baseline: 1.1024x; 1.1024x over previous
#include <cuda_runtime.h>
#include <math.h>

typedef unsigned long long ull;

#define BATCH 2048
#define HGT 7
#define WID 24
#define PIX 168            // 7*24
#define SROW 28            // padded row width (24 + halo + align pad), 16B aligned
#define SPLANE (9*SROW)    // 252 floats per channel plane (7 rows + halo)

#define C0IN 2
#define HC0 32
#define HC1 64

// ---------------- scratch (static device allocations; no cudaMalloc) ----------------
__device__ float g_gx0[(size_t)BATCH * 128 * PIX];        // conv(input,Wx0)+bx0, time-invariant
__device__ float g_h0[2][(size_t)BATCH * HC0 * PIX];      // ping-pong hidden, layer 0
__device__ float g_c0[(size_t)BATCH * HC0 * PIX];         // cell state layer 0 (in-place)
__device__ float g_h1[2][(size_t)BATCH * HC1 * PIX];      // ping-pong hidden, layer 1
__device__ float g_c1[(size_t)BATCH * HC1 * PIX];         // cell state layer 1 (in-place)
__device__ float g_fcwT[10752 * 64];                      // fc1_w transposed, o-paired layout

// transformed conv weights: [hc][ic][k=0..8][gate=0..3][dup=0..1]  (pair-duplicated for f32x2)
__device__ __align__(16) float g_wt0d[HC0 * HC0 * 9 * 8];          // 73728
__device__ __align__(16) float g_wt1d[HC1 * (HC0 + HC1) * 9 * 8];  // 442368

// ---------------- f32x2 helpers ----------------
__device__ __forceinline__ ull pk2(float lo, float hi) {
    ull r;
    asm("mov.b64 %0, {%1, %2};" : "=l"(r) : "f"(lo), "f"(hi));
    return r;
}
__device__ __forceinline__ void upk2(ull p, float& lo, float& hi) {
    asm("mov.b64 {%0, %1}, %2;" : "=f"(lo), "=f"(hi) : "l"(p));
}
__device__ __forceinline__ ull ffma2(ull a, ull b, ull c) {
    ull d;
    asm("fma.rn.f32x2 %0, %1, %2, %3;" : "=l"(d) : "l"(a), "l"(b), "l"(c));
    return d;
}
__device__ __forceinline__ float sigf(float x) { return 1.f / (1.f + expf(-x)); }

// ---------------- init ----------------
__global__ void k_zero() {
    size_t stride = (size_t)gridDim.x * blockDim.x;
    size_t gid = (size_t)blockIdx.x * blockDim.x + threadIdx.x;
    const size_t N0 = (size_t)BATCH * HC0 * PIX;
    const size_t N1 = (size_t)BATCH * HC1 * PIX;
    for (size_t i = gid; i < N0; i += stride) { g_h0[0][i] = 0.f; g_c0[i] = 0.f; }
    for (size_t i = gid; i < N1; i += stride) { g_h1[0][i] = 0.f; g_c1[i] = 0.f; }
}

// ---------------- weight transform: gate-packed + pair-duplicated ----------------
__global__ void k_wtg(const float* __restrict__ Wh0, const float* __restrict__ Wx1,
                      const float* __restrict__ Wh1) {
    int idx = blockIdx.x * blockDim.x + threadIdx.x;
    const int N0 = HC0 * HC0 * 9 * 8;
    const int N1 = HC1 * (HC0 + HC1) * 9 * 8;
    if (idx < N0) {
        int g = (idx >> 1) & 3;
        int t = idx >> 3;            // (hc*32+ic)*9 + k
        int k = t % 9;
        int rest = t / 9;
        int ic = rest % HC0, hc = rest / HC0;
        g_wt0d[idx] = Wh0[((g * HC0 + hc) * HC0 + ic) * 9 + k];
    } else if (idx < N0 + N1) {
        int j = idx - N0;
        int g = (j >> 1) & 3;
        int t = j >> 3;
        int k = t % 9;
        int rest = t / 9;
        int ic = rest % 96, hc = rest / 96;
        float v = (ic < HC0) ? Wx1[((g * HC1 + hc) * HC0 + ic) * 9 + k]
                             : Wh1[((g * HC1 + hc) * HC1 + (ic - HC0)) * 9 + k];
        g_wt1d[j] = v;
    }
}

// ---------------- gx0 = conv(input, Wx0) + bx0 (once) ----------------
__global__ void k_gx0(const float* __restrict__ input, const float* __restrict__ Wx0,
                      const float* __restrict__ bx0) {
    __shared__ float sin_[C0IN * SPLANE];
    int b = blockIdx.x, tid = threadIdx.x;
    for (int i = tid; i < C0IN * SPLANE; i += blockDim.x) sin_[i] = 0.f;
    __syncthreads();
    for (int u = tid; u < C0IN * PIX; u += blockDim.x) {
        int ic = u / PIX, pix = u % PIX, y = pix / WID, x = pix % WID;
        sin_[ic * SPLANE + (y + 1) * SROW + (x + 1)] = input[(size_t)b * C0IN * PIX + u];
    }
    __syncthreads();
    for (int u = tid; u < 128 * PIX; u += blockDim.x) {
        int oc = u / PIX, pix = u % PIX, y = pix / WID, x = pix % WID;
        float acc = bx0[oc];
#pragma unroll
        for (int ic = 0; ic < C0IN; ic++)
#pragma unroll
            for (int ky = 0; ky < 3; ky++)
#pragma unroll
                for (int kx = 0; kx < 3; kx++)
                    acc += sin_[ic * SPLANE + (y + ky) * SROW + (x + kx)] *
                           __ldg(&Wx0[oc * 18 + ic * 9 + ky * 3 + kx]);
        g_gx0[(size_t)b * 128 * PIX + u] = acc;
    }
}

// ---------------- packed conv core: 12 pixels, 4 gates, f32x2 ----------------
// Wt points at this hc's weights: [ic][k][gate][2] (72 floats per ic).
// sh holds C zero-padded planes (SPLANE floats each, data at col x+1, row y+1).
template <int C>
__device__ __forceinline__ void conv12(const float* __restrict__ Wt, const float* sh,
                                       int row, int xb, ull (&acc)[4][6]) {
#pragma unroll 1
    for (int ic = 0; ic < C; ic++) {
        const float* plane = sh + ic * SPLANE;
        const float* wb = Wt + ic * 72;
#pragma unroll
        for (int ky = 0; ky < 3; ky++) {
            const float* srow = plane + (row + ky) * SROW + xb;
            // aligned pixel pairs A[0..6] = (v0,v1)(v2,v3)...(v12,v13)
            ull A[7];
            ulonglong2 m;
            m = *(const ulonglong2*)(srow);     A[0] = m.x; A[1] = m.y;
            m = *(const ulonglong2*)(srow + 4); A[2] = m.x; A[3] = m.y;
            m = *(const ulonglong2*)(srow + 8); A[4] = m.x; A[5] = m.y;
            A[6] = *(const ull*)(srow + 12);
            float v[14];
#pragma unroll
            for (int j = 0; j < 7; j++) upk2(A[j], v[2 * j], v[2 * j + 1]);
            // odd pairs O[0..5] = (v1,v2)(v3,v4)...(v11,v12)
            ull O[6];
#pragma unroll
            for (int j = 0; j < 6; j++) O[j] = pk2(v[2 * j + 1], v[2 * j + 2]);
            const float* wk = wb + ky * 24;
#pragma unroll
            for (int kx = 0; kx < 3; kx++) {
                ulonglong2 w01 = __ldg((const ulonglong2*)(wk + kx * 8));
                ulonglong2 w23 = __ldg((const ulonglong2*)(wk + kx * 8 + 4));
#pragma unroll
                for (int q = 0; q < 6; q++) {
                    ull vp = (kx == 1) ? O[q] : A[q + (kx >> 1)];
                    acc[0][q] = ffma2(vp, w01.x, acc[0][q]);
                    acc[1][q] = ffma2(vp, w01.y, acc[1][q]);
                    acc[2][q] = ffma2(vp, w23.x, acc[2][q]);
                    acc[3][q] = ffma2(vp, w23.y, acc[3][q]);
                }
            }
        }
    }
}

// gate epilogue over 12 pixels
template <int HC>
__device__ __forceinline__ void gate12(ull (&acc)[4][6], float* cptr, float* hptr,
                                       const float* wc) {
    float a0[12], a1[12], a2[12], a3[12];
#pragma unroll
    for (int q = 0; q < 6; q++) {
        upk2(acc[0][q], a0[2 * q], a0[2 * q + 1]);
        upk2(acc[1][q], a1[2 * q], a1[2 * q + 1]);
        upk2(acc[2][q], a2[2 * q], a2[2 * q + 1]);
        upk2(acc[3][q], a3[2 * q], a3[2 * q + 1]);
    }
#pragma unroll
    for (int p = 0; p < 12; p++) {
        float c = cptr[p];
        float ci = sigf(a0[p] + c * wc[p]);
        float cf = sigf(a1[p] + c * wc[HC * PIX + p]);
        float cc = cf * c + ci * tanhf(a2[p]);
        float co = sigf(a3[p] + cc * wc[2 * HC * PIX + p]);
        cptr[p] = cc;
        hptr[p] = co * tanhf(cc);
    }
}

// ---------------- layer-0 cell step ----------------
__global__ void __launch_bounds__(224, 2)
k_cell0(const float* __restrict__ Wc0, int s) {
    extern __shared__ float sh[];  // HC0 * SPLANE
    int b = blockIdx.x, tid = threadIdx.x;
    int src = s & 1, dst = src ^ 1;
    // zero (vectorized) then load interior
    float4 z = make_float4(0.f, 0.f, 0.f, 0.f);
    for (int i = tid; i < HC0 * SPLANE / 4; i += 224) ((float4*)sh)[i] = z;
    __syncthreads();
    const float* h0s = g_h0[src] + (size_t)b * HC0 * PIX;
    for (int u = tid; u < HC0 * 7 * 6; u += 224) {
        int ch = u / 42, rem = u % 42, r = rem / 6, j = rem % 6;
        float4 vv = *(const float4*)(h0s + ch * PIX + r * WID + j * 4);
        float* d = sh + ch * SPLANE + (r + 1) * SROW + 1 + j * 4;
        d[0] = vv.x; d[1] = vv.y; d[2] = vv.z; d[3] = vv.w;
    }
    __syncthreads();
    const float* gx = g_gx0 + (size_t)b * 128 * PIX;
#pragma unroll 1
    for (int it = 0; it < 2; it++) {           // 32*14 = 448 tasks
        int task = tid + it * 224;
        int hc = task / 14, g12 = task % 14;
        int row = g12 >> 1, xb = (g12 & 1) * 12;
        int pixbase = row * WID + xb;
        ull acc[4][6];
#pragma unroll
        for (int g = 0; g < 4; g++) {
            const float* gp = gx + ((size_t)(g * HC0 + hc)) * PIX + pixbase;
            float4 x0 = *(const float4*)(gp);
            float4 x1 = *(const float4*)(gp + 4);
            float4 x2 = *(const float4*)(gp + 8);
            acc[g][0] = pk2(x0.x, x0.y); acc[g][1] = pk2(x0.z, x0.w);
            acc[g][2] = pk2(x1.x, x1.y); acc[g][3] = pk2(x1.z, x1.w);
            acc[g][4] = pk2(x2.x, x2.y); acc[g][5] = pk2(x2.z, x2.w);
        }
        conv12<HC0>(g_wt0d + hc * HC0 * 72, sh, row, xb, acc);
        float* cptr = g_c0 + ((size_t)b * HC0 + hc) * PIX + pixbase;
        float* hptr = g_h0[dst] + ((size_t)b * HC0 + hc) * PIX + pixbase;
        gate12<HC0>(acc, cptr, hptr, Wc0 + hc * PIX + pixbase);
    }
}

// ---------------- layer-1 cell step ----------------
__global__ void __launch_bounds__(224, 2)
k_cell1(const float* __restrict__ bx1, const float* __restrict__ Wc1, int s) {
    extern __shared__ float sh[];  // 96 * SPLANE
    int b = blockIdx.x, tid = threadIdx.x;
    int src = s & 1, dst = src ^ 1;
    const float* h0n = g_h0[dst] + (size_t)b * HC0 * PIX;  // freshly written by k_cell0
    const float* h1s = g_h1[src] + (size_t)b * HC1 * PIX;
    float4 z = make_float4(0.f, 0.f, 0.f, 0.f);
    for (int i = tid; i < 96 * SPLANE / 4; i += 224) ((float4*)sh)[i] = z;
    __syncthreads();
    for (int u = tid; u < 96 * 7 * 6; u += 224) {
        int ch = u / 42, rem = u % 42, r = rem / 6, j = rem % 6;
        const float* srcp = (ch < HC0) ? (h0n + ch * PIX) : (h1s + (ch - HC0) * PIX);
        float4 vv = *(const float4*)(srcp + r * WID + j * 4);
        float* d = sh + ch * SPLANE + (r + 1) * SROW + 1 + j * 4;
        d[0] = vv.x; d[1] = vv.y; d[2] = vv.z; d[3] = vv.w;
    }
    __syncthreads();
#pragma unroll 1
    for (int it = 0; it < 4; it++) {           // 64*14 = 896 tasks
        int task = tid + it * 224;
        int hc = task / 14, g12 = task % 14;
        int row = g12 >> 1, xb = (g12 & 1) * 12;
        int pixbase = row * WID + xb;
        ull acc[4][6];
#pragma unroll
        for (int g = 0; g < 4; g++) {
            float bv = __ldg(&bx1[g * HC1 + hc]);
            ull bp = pk2(bv, bv);
#pragma unroll
            for (int q = 0; q < 6; q++) acc[g][q] = bp;
        }
        conv12<96>(g_wt1d + hc * 96 * 72, sh, row, xb, acc);
        float* cptr = g_c1 + ((size_t)b * HC1 + hc) * PIX + pixbase;
        float* hptr = g_h1[dst] + ((size_t)b * HC1 + hc) * PIX + pixbase;
        gate12<HC1>(acc, cptr, hptr, Wc1 + hc * PIX + pixbase);
    }
}

// ---------------- fc1 weight transpose ----------------
__global__ void k_wt(const float* __restrict__ fc1_w) {
    int idx = blockIdx.x * blockDim.x + threadIdx.x;
    if (idx >= 10752 * 64) return;
    int k = idx / 64, o = idx % 64;
    g_fcwT[k * 64 + (o & 31) * 2 + (o >> 5)] = fc1_w[(size_t)o * 10752 + k];
}

// ---------------- fc1 head: out[:, 0:64] ----------------
__global__ void k_fc(const float* __restrict__ fc1_b, float* __restrict__ out) {
    __shared__ float shh[8 * 1344];
    int tid = threadIdx.x;
    int b0 = blockIdx.x * 8;
    int it = tid >> 5, o = tid & 31;
    float acc0 = 0.f, acc1 = 0.f;
    const float* h1f = g_h1[1];        // after 7 steps final h1 lives in buffer 1
#pragma unroll 1
    for (int cb = 0; cb < 8; cb++) {
        __syncthreads();
        for (int u = tid; u < 8 * 1344; u += 256) {
            int i2 = u / 1344, kk = u % 1344;
            shh[u] = h1f[(size_t)(b0 + i2) * 10752 + cb * 1344 + kk];
        }
        __syncthreads();
        const float* wp = g_fcwT + (size_t)cb * 1344 * 64 + o * 2;
        const float* hp = shh + it * 1344;
#pragma unroll 4
        for (int kk = 0; kk < 1344; kk++) {
            float hv = hp[kk];
            float2 w2 = __ldg((const float2*)(wp + (size_t)kk * 64));
            acc0 = fmaf(hv, w2.x, acc0);
            acc1 = fmaf(hv, w2.y, acc1);
        }
    }
    out[(size_t)(b0 + it) * 128 + o] = fmaxf(acc0 + fc1_b[o], 0.f);
    out[(size_t)(b0 + it) * 128 + o + 32] = fmaxf(acc1 + fc1_b[o + 32], 0.f);
}

// ---------------- exfc head: out[:, 64:128] ----------------
__global__ void k_exfc(const float* __restrict__ x_ex, const float* __restrict__ w,
                       const float* __restrict__ bias, float* __restrict__ out) {
    int idx = blockIdx.x * blockDim.x + threadIdx.x;
    if (idx >= BATCH * 64) return;
    int b = idx >> 6, o = idx & 63;
    float acc = bias[o];
#pragma unroll
    for (int k = 0; k < 24; k++) acc += x_ex[b * 24 + k] * __ldg(&w[o * 24 + k]);
    out[(size_t)b * 128 + 64 + o] = fmaxf(acc, 0.f);
}

// ---------------- launch ----------------
extern "C" void kernel_launch(void* const* d_in, const int* in_sizes, int n_in,
                              void* d_out, int out_size) {
    const float* input  = (const float*)d_in[0];
    const float* x_ex   = (const float*)d_in[1];
    const float* Wx0    = (const float*)d_in[2];
    const float* bx0    = (const float*)d_in[3];
    const float* Wh0    = (const float*)d_in[4];
    const float* Wc0    = (const float*)d_in[5];
    const float* Wx1    = (const float*)d_in[6];
    const float* bx1    = (const float*)d_in[7];
    const float* Wh1    = (const float*)d_in[8];
    const float* Wc1    = (const float*)d_in[9];
    const float* fc1_w  = (const float*)d_in[10];
    const float* fc1_b  = (const float*)d_in[11];
    const float* exfc_w = (const float*)d_in[12];
    const float* exfc_b = (const float*)d_in[13];
    float* out = (float*)d_out;

    (void)in_sizes; (void)n_in; (void)out_size;

    cudaFuncSetAttribute(k_cell1, cudaFuncAttributeMaxDynamicSharedMemorySize,
                         96 * SPLANE * (int)sizeof(float));

    k_zero<<<4096, 256>>>();
    k_gx0<<<BATCH, 256>>>(input, Wx0, bx0);
    k_wt<<<(10752 * 64 + 255) / 256, 256>>>(fc1_w);
    {
        int ntr = HC0 * HC0 * 9 * 8 + HC1 * 96 * 9 * 8;
        k_wtg<<<(ntr + 255) / 256, 256>>>(Wh0, Wx1, Wh1);
    }

    for (int s = 0; s < 7; s++) {
        k_cell0<<<BATCH, 224, HC0 * SPLANE * (int)sizeof(float)>>>(Wc0, s);
        k_cell1<<<BATCH, 224, 96 * SPLANE * (int)sizeof(float)>>>(bx1, Wc1, s);
    }

    k_fc<<<BATCH / 8, 256>>>(fc1_b, out);
    k_exfc<<<(BATCH * 64 + 255) / 256, 256>>>(x_ex, exfc_w, exfc_b, out);
}

// round 7
// speedup vs baseline: 2.6257x; 2.3818x over previous
#include <cuda_runtime.h>
#include <cuda_fp16.h>
#include <math.h>

typedef unsigned long long ull;
typedef unsigned int uint;

#define BATCH 2048
#define HGT 7
#define WID 24
#define PIX 168            // 7*24
#define SROW 28            // padded row width for SIMT cell0 planes
#define SPLANE (9*SROW)

#define C0IN 2
#define HC0 32
#define HC1 64

// cell1 tensor-core geometry
#define P1ROW 26           // padded cols (24 + halo)
#define P1CH 96            // 32 h0 + 64 h1 channels, contiguous (= GEMM K inner)
#define P1HALVES (9*P1ROW*P1CH)     // 22464 halves = 44928 B
#define WBUF_N 264         // 256 + 8 pad (LDSM bank spread)
#define NCHUNK 54          // 9 taps * 6 ic16-chunks

// ---------------- scratch ----------------
__device__ float  g_gx0[(size_t)BATCH * 128 * PIX];
__device__ float  g_h0[2][(size_t)BATCH * HC0 * PIX];
__device__ float  g_c0[(size_t)BATCH * HC0 * PIX];
__device__ __half g_h1[2][(size_t)BATCH * PIX * HC1];   // [item][pix][hc] fp16
__device__ float  g_c1[(size_t)BATCH * PIX * HC1];      // [item][pix][hc] fp32
__device__ float  g_fcwT[10752 * 64];
__device__ __align__(16) float  g_wt0d[HC0 * HC0 * 9 * 8];        // SIMT cell0 weights
__device__ __align__(16) __half g_w1h[NCHUNK * 16 * 256];         // cell1 fp16 [chunk][k16][n256]

// ---------------- helpers ----------------
typedef unsigned long long u64;
__device__ __forceinline__ ull pk2(float lo, float hi) {
    ull r; asm("mov.b64 %0, {%1, %2};" : "=l"(r) : "f"(lo), "f"(hi)); return r;
}
__device__ __forceinline__ void upk2(ull p, float& lo, float& hi) {
    asm("mov.b64 {%0, %1}, %2;" : "=f"(lo), "=f"(hi) : "l"(p));
}
__device__ __forceinline__ ull ffma2(ull a, ull b, ull c) {
    ull d; asm("fma.rn.f32x2 %0, %1, %2, %3;" : "=l"(d) : "l"(a), "l"(b), "l"(c)); return d;
}
__device__ __forceinline__ float sigf(float x) { return 1.f / (1.f + expf(-x)); }
__device__ __forceinline__ uint smem_u32(const void* p) {
    uint a;
    asm("{ .reg .u64 t; cvta.to.shared.u64 t, %1; cvt.u32.u64 %0, t; }" : "=r"(a) : "l"(p));
    return a;
}

// ---------------- init ----------------
__global__ void k_zero() {
    size_t stride = (size_t)gridDim.x * blockDim.x;
    size_t gid = (size_t)blockIdx.x * blockDim.x + threadIdx.x;
    const size_t N0 = (size_t)BATCH * HC0 * PIX;
    const size_t N1 = (size_t)BATCH * PIX * HC1;
    for (size_t i = gid; i < N0; i += stride) { g_h0[0][i] = 0.f; g_c0[i] = 0.f; }
    for (size_t i = gid; i < N1; i += stride) { g_c1[i] = 0.f; }
    uint* h1z = (uint*)g_h1[0];
    for (size_t i = gid; i < N1 / 2; i += stride) h1z[i] = 0u;
}

// ---------------- cell0 SIMT weight transform ----------------
__global__ void k_wtg(const float* __restrict__ Wh0) {
    int idx = blockIdx.x * blockDim.x + threadIdx.x;
    if (idx >= HC0 * HC0 * 9 * 8) return;
    int g = (idx >> 1) & 3;
    int t = idx >> 3;
    int k = t % 9;
    int rest = t / 9;
    int ic = rest % HC0, hc = rest / HC0;
    g_wt0d[idx] = Wh0[((g * HC0 + hc) * HC0 + ic) * 9 + k];
}

// ---------------- cell1 fp16 weight transform: [chunk=tap*6+icc][k16][n=hc*4+g] ----------------
__global__ void k_w1h(const float* __restrict__ Wx1, const float* __restrict__ Wh1) {
    int idx = blockIdx.x * blockDim.x + threadIdx.x;
    if (idx >= NCHUNK * 16 * 256) return;
    int chunk = idx / 4096;
    int rem = idx % 4096;
    int k = rem / 256, n = rem % 256;
    int tap = chunk / 6, icc = chunk % 6;
    int ic = icc * 16 + k;
    int hc = n / 4, g = n % 4;
    float v = (ic < HC0) ? Wx1[((g * HC1 + hc) * HC0 + ic) * 9 + tap]
                         : Wh1[((g * HC1 + hc) * HC1 + (ic - HC0)) * 9 + tap];
    g_w1h[idx] = __float2half(v);
}

// ---------------- gx0 = conv(input, Wx0) + bx0 (once) ----------------
__global__ void k_gx0(const float* __restrict__ input, const float* __restrict__ Wx0,
                      const float* __restrict__ bx0) {
    __shared__ float sin_[C0IN * SPLANE];
    int b = blockIdx.x, tid = threadIdx.x;
    for (int i = tid; i < C0IN * SPLANE; i += blockDim.x) sin_[i] = 0.f;
    __syncthreads();
    for (int u = tid; u < C0IN * PIX; u += blockDim.x) {
        int ic = u / PIX, pix = u % PIX, y = pix / WID, x = pix % WID;
        sin_[ic * SPLANE + (y + 1) * SROW + (x + 1)] = input[(size_t)b * C0IN * PIX + u];
    }
    __syncthreads();
    for (int u = tid; u < 128 * PIX; u += blockDim.x) {
        int oc = u / PIX, pix = u % PIX, y = pix / WID, x = pix % WID;
        float acc = bx0[oc];
#pragma unroll
        for (int ic = 0; ic < C0IN; ic++)
#pragma unroll
            for (int ky = 0; ky < 3; ky++)
#pragma unroll
                for (int kx = 0; kx < 3; kx++)
                    acc += sin_[ic * SPLANE + (y + ky) * SROW + (x + kx)] *
                           __ldg(&Wx0[oc * 18 + ic * 9 + ky * 3 + kx]);
        g_gx0[(size_t)b * 128 * PIX + u] = acc;
    }
}

// ---------------- SIMT conv core (cell0, unchanged from R4) ----------------
template <int C>
__device__ __forceinline__ void conv12(const float* __restrict__ Wt, const float* sh,
                                       int row, int xb, ull (&acc)[4][6]) {
#pragma unroll 1
    for (int ic = 0; ic < C; ic++) {
        const float* plane = sh + ic * SPLANE;
        const float* wb = Wt + ic * 72;
#pragma unroll
        for (int ky = 0; ky < 3; ky++) {
            const float* srow = plane + (row + ky) * SROW + xb;
            ull A[7];
            ulonglong2 m;
            m = *(const ulonglong2*)(srow);     A[0] = m.x; A[1] = m.y;
            m = *(const ulonglong2*)(srow + 4); A[2] = m.x; A[3] = m.y;
            m = *(const ulonglong2*)(srow + 8); A[4] = m.x; A[5] = m.y;
            A[6] = *(const ull*)(srow + 12);
            float v[14];
#pragma unroll
            for (int j = 0; j < 7; j++) upk2(A[j], v[2 * j], v[2 * j + 1]);
            ull O[6];
#pragma unroll
            for (int j = 0; j < 6; j++) O[j] = pk2(v[2 * j + 1], v[2 * j + 2]);
            const float* wk = wb + ky * 24;
#pragma unroll
            for (int kx = 0; kx < 3; kx++) {
                ulonglong2 w01 = __ldg((const ulonglong2*)(wk + kx * 8));
                ulonglong2 w23 = __ldg((const ulonglong2*)(wk + kx * 8 + 4));
#pragma unroll
                for (int q = 0; q < 6; q++) {
                    ull vp = (kx == 1) ? O[q] : A[q + (kx >> 1)];
                    acc[0][q] = ffma2(vp, w01.x, acc[0][q]);
                    acc[1][q] = ffma2(vp, w01.y, acc[1][q]);
                    acc[2][q] = ffma2(vp, w23.x, acc[2][q]);
                    acc[3][q] = ffma2(vp, w23.y, acc[3][q]);
                }
            }
        }
    }
}

template <int HC>
__device__ __forceinline__ void gate12(ull (&acc)[4][6], float* cptr, float* hptr,
                                       const float* wc) {
    float a0[12], a1[12], a2[12], a3[12];
#pragma unroll
    for (int q = 0; q < 6; q++) {
        upk2(acc[0][q], a0[2 * q], a0[2 * q + 1]);
        upk2(acc[1][q], a1[2 * q], a1[2 * q + 1]);
        upk2(acc[2][q], a2[2 * q], a2[2 * q + 1]);
        upk2(acc[3][q], a3[2 * q], a3[2 * q + 1]);
    }
#pragma unroll
    for (int p = 0; p < 12; p++) {
        float c = cptr[p];
        float ci = sigf(a0[p] + c * wc[p]);
        float cf = sigf(a1[p] + c * wc[HC0 * PIX + p]);
        float cc = cf * c + ci * tanhf(a2[p]);
        float co = sigf(a3[p] + cc * wc[2 * HC0 * PIX + p]);
        cptr[p] = cc;
        hptr[p] = co * tanhf(cc);
    }
}

// ---------------- layer-0 cell step (SIMT, fp32) ----------------
__global__ void __launch_bounds__(224, 2)
k_cell0(const float* __restrict__ Wc0, int s) {
    extern __shared__ float sh[];  // HC0 * SPLANE
    int b = blockIdx.x, tid = threadIdx.x;
    int src = s & 1, dst = src ^ 1;
    float4 z = make_float4(0.f, 0.f, 0.f, 0.f);
    for (int i = tid; i < HC0 * SPLANE / 4; i += 224) ((float4*)sh)[i] = z;
    __syncthreads();
    const float* h0s = g_h0[src] + (size_t)b * HC0 * PIX;
    for (int u = tid; u < HC0 * 7 * 6; u += 224) {
        int ch = u / 42, rem = u % 42, r = rem / 6, j = rem % 6;
        float4 vv = *(const float4*)(h0s + ch * PIX + r * WID + j * 4);
        float* d = sh + ch * SPLANE + (r + 1) * SROW + 1 + j * 4;
        d[0] = vv.x; d[1] = vv.y; d[2] = vv.z; d[3] = vv.w;
    }
    __syncthreads();
    const float* gx = g_gx0 + (size_t)b * 128 * PIX;
#pragma unroll 1
    for (int it = 0; it < 2; it++) {
        int task = tid + it * 224;
        int hc = task / 14, g12 = task % 14;
        int row = g12 >> 1, xb = (g12 & 1) * 12;
        int pixbase = row * WID + xb;
        ull acc[4][6];
#pragma unroll
        for (int g = 0; g < 4; g++) {
            const float* gp = gx + ((size_t)(g * HC0 + hc)) * PIX + pixbase;
            float4 x0 = *(const float4*)(gp);
            float4 x1 = *(const float4*)(gp + 4);
            float4 x2 = *(const float4*)(gp + 8);
            acc[g][0] = pk2(x0.x, x0.y); acc[g][1] = pk2(x0.z, x0.w);
            acc[g][2] = pk2(x1.x, x1.y); acc[g][3] = pk2(x1.z, x1.w);
            acc[g][4] = pk2(x2.x, x2.y); acc[g][5] = pk2(x2.z, x2.w);
        }
        conv12<HC0>(g_wt0d + hc * HC0 * 72, sh, row, xb, acc);
        float* cptr = g_c0 + ((size_t)b * HC0 + hc) * PIX + pixbase;
        float* hptr = g_h0[dst] + ((size_t)b * HC0 + hc) * PIX + pixbase;
        gate12<HC0>(acc, cptr, hptr, Wc0 + hc * PIX + pixbase);
    }
}

// ---------------- layer-1 cell step: tensor-core implicit GEMM ----------------
__global__ void __launch_bounds__(512, 1)
k_cell1tc(const float* __restrict__ bx1, const float* __restrict__ Wc1, int s) {
    extern __shared__ __align__(16) char smraw[];
    __half* plane = (__half*)smraw;                              // P1HALVES
    __half* wbuf = (__half*)(smraw + P1HALVES * 2);              // 2 * 16 * WBUF_N
    int b = blockIdx.x, tid = threadIdx.x;
    int src = s & 1, dst = src ^ 1;

    // ---- build fp16 halo plane [9][26][96]: ch 0-31 = h0_new, 32-95 = h1_old ----
    uint4 z4; z4.x = z4.y = z4.z = z4.w = 0u;
    for (int i = tid; i < P1HALVES / 8; i += 512) ((uint4*)plane)[i] = z4;
    __syncthreads();
    const float* h0n = g_h0[dst] + (size_t)b * HC0 * PIX;        // fresh from cell0
    for (int u = tid; u < HC0 * PIX; u += 512) {
        int ch = u / PIX, pix = u % PIX;
        int y = pix / WID, x = pix % WID;
        plane[((y + 1) * P1ROW + (x + 1)) * P1CH + ch] = __float2half(h0n[ch * PIX + pix]);
    }
    const __half* h1s = g_h1[src] + (size_t)b * PIX * HC1;
    for (int u = tid; u < PIX * 8; u += 512) {
        int pix = u / 8, seg = u % 8;
        int y = pix / WID, x = pix % WID;
        uint4 v = *(const uint4*)(h1s + pix * HC1 + seg * 8);
        *(uint4*)(plane + ((y + 1) * P1ROW + (x + 1)) * P1CH + 32 + seg * 8) = v;
    }

    // ---- stage weight chunk 0 ----
    {
        uint4 v = *(const uint4*)(g_w1h + tid * 8);
        *(uint4*)(wbuf + (tid >> 5) * WBUF_N + (tid & 31) * 8) = v;
    }
    __syncthreads();

    uint planeU = smem_u32(plane);
    uint wbufU = smem_u32(wbuf);
    int lane = tid & 31, warp = tid >> 5;
    int mg = warp >> 2, ng = warp & 3;      // 4 M-groups x 4 N-groups(n64)

    // per-lane A row base (center offset in 26-col units) for 3 m16 tiles
    int base26[3];
#pragma unroll
    for (int mt = 0; mt < 3; mt++) {
        int p = (mg * 3 + mt) * 16 + (lane & 15);
        if (p > 167) p = 167;               // clamp; results discarded in epilogue
        int y = p / WID, x = p % WID;
        base26[mt] = (y + 1) * P1ROW + (x + 1);
    }
    uint ahi = (uint)((lane >> 4) * 16);    // k-half byte offset
    int bk = lane & 15;                     // B ldmatrix row (k)
    uint bsel = (uint)(((lane >> 4) * 8 + ng * 64) * 2);  // B col byte offset

    float d[3][8][4];
#pragma unroll
    for (int mt = 0; mt < 3; mt++)
#pragma unroll
        for (int j = 0; j < 8; j++)
#pragma unroll
            for (int q = 0; q < 4; q++) d[mt][j][q] = 0.f;

    // ---- K loop: 54 chunks (tap-major), double-buffered weight staging ----
#pragma unroll 1
    for (int c = 0; c < NCHUNK; c++) {
        if (c + 1 < NCHUNK) {
            uint4 v = *(const uint4*)(g_w1h + (size_t)(c + 1) * 4096 + tid * 8);
            __half* wb = wbuf + ((c + 1) & 1) * (16 * WBUF_N);
            *(uint4*)(wb + (tid >> 5) * WBUF_N + (tid & 31) * 8) = v;
        }
        int tap = c / 6, icc = c % 6;
        int tapoff = (tap / 3 - 1) * P1ROW + (tap % 3 - 1);
        uint wU = wbufU + (uint)((c & 1) * (16 * WBUF_N * 2));

        uint a[3][4];
#pragma unroll
        for (int mt = 0; mt < 3; mt++) {
            uint aaddr = planeU + (uint)((base26[mt] + tapoff) * (P1CH * 2)) + (uint)(icc * 32) + ahi;
            asm volatile("ldmatrix.sync.aligned.m8n8.x4.shared.b16 {%0,%1,%2,%3}, [%4];"
                         : "=r"(a[mt][0]), "=r"(a[mt][1]), "=r"(a[mt][2]), "=r"(a[mt][3])
                         : "r"(aaddr));
        }
#pragma unroll
        for (int np = 0; np < 4; np++) {
            uint baddr = wU + (uint)(bk * WBUF_N * 2) + bsel + (uint)(np * 32);
            uint b0, b1, b2, b3;
            asm volatile("ldmatrix.sync.aligned.m8n8.x4.trans.shared.b16 {%0,%1,%2,%3}, [%4];"
                         : "=r"(b0), "=r"(b1), "=r"(b2), "=r"(b3) : "r"(baddr));
#pragma unroll
            for (int mt = 0; mt < 3; mt++) {
                asm volatile("mma.sync.aligned.m16n8k16.row.col.f32.f16.f16.f32 "
                             "{%0,%1,%2,%3}, {%4,%5,%6,%7}, {%8,%9}, {%0,%1,%2,%3};"
                             : "+f"(d[mt][2 * np][0]), "+f"(d[mt][2 * np][1]),
                               "+f"(d[mt][2 * np][2]), "+f"(d[mt][2 * np][3])
                             : "r"(a[mt][0]), "r"(a[mt][1]), "r"(a[mt][2]), "r"(a[mt][3]),
                               "r"(b0), "r"(b1));
                asm volatile("mma.sync.aligned.m16n8k16.row.col.f32.f16.f16.f32 "
                             "{%0,%1,%2,%3}, {%4,%5,%6,%7}, {%8,%9}, {%0,%1,%2,%3};"
                             : "+f"(d[mt][2 * np + 1][0]), "+f"(d[mt][2 * np + 1][1]),
                               "+f"(d[mt][2 * np + 1][2]), "+f"(d[mt][2 * np + 1][3])
                             : "r"(a[mt][0]), "r"(a[mt][1]), "r"(a[mt][2]), "r"(a[mt][3]),
                               "r"(b2), "r"(b3));
            }
        }
        __syncthreads();
    }

    // ---- epilogue: gather 4 gates per (pixel,hc) via bfly shuffle, LSTM pointwise ----
    float* c1f = g_c1 + (size_t)b * PIX * HC1;
    __half* h1d = g_h1[dst] + (size_t)b * PIX * HC1;
    int t = lane & 3, r = lane >> 2;
    int odd = t & 1;
#pragma unroll
    for (int mt = 0; mt < 3; mt++) {
        int tile = mg * 3 + mt;
#pragma unroll
        for (int j = 0; j < 8; j++) {
            float v0 = d[mt][j][0], v1 = d[mt][j][1], v2 = d[mt][j][2], v3 = d[mt][j][3];
            float x0 = __shfl_xor_sync(0xffffffffu, v0, 1);
            float x1 = __shfl_xor_sync(0xffffffffu, v1, 1);
            float x2 = __shfl_xor_sync(0xffffffffu, v2, 1);
            float x3 = __shfl_xor_sync(0xffffffffu, v3, 1);
            int pixel = tile * 16 + r + odd * 8;
            int hc = ng * 16 + j * 2 + (t >> 1);
            float gi = odd ? x2 : v0;
            float gf = odd ? x3 : v1;
            float gc = odd ? v2 : x0;
            float go = odd ? v3 : x1;
            if (pixel < PIX) {
                gi += __ldg(&bx1[hc]);
                gf += __ldg(&bx1[64 + hc]);
                gc += __ldg(&bx1[128 + hc]);
                go += __ldg(&bx1[192 + hc]);
                float cold = c1f[pixel * HC1 + hc];
                float w0 = __ldg(&Wc1[hc * PIX + pixel]);
                float w1 = __ldg(&Wc1[10752 + hc * PIX + pixel]);
                float w2 = __ldg(&Wc1[21504 + hc * PIX + pixel]);
                float ci = sigf(gi + cold * w0);
                float cf = sigf(gf + cold * w1);
                float cc = cf * cold + ci * tanhf(gc);
                float co = sigf(go + cc * w2);
                c1f[pixel * HC1 + hc] = cc;
                h1d[pixel * HC1 + hc] = __float2half(co * tanhf(cc));
            }
        }
    }
}

// ---------------- fc1 weight transpose: k index follows new [pix][ch] flatten ----------------
__global__ void k_wt(const float* __restrict__ fc1_w) {
    int idx = blockIdx.x * blockDim.x + threadIdx.x;
    if (idx >= 10752 * 64) return;
    int k = idx / 64, o = idx % 64;       // k = pix*64 + ch
    int pix = k / 64, ch = k % 64;
    g_fcwT[k * 64 + (o & 31) * 2 + (o >> 5)] = fc1_w[(size_t)o * 10752 + ch * PIX + pix];
}

// ---------------- fc1 head: out[:, 0:64] ----------------
__global__ void k_fc(const float* __restrict__ fc1_b, float* __restrict__ out) {
    __shared__ float shh[8 * 1344];
    int tid = threadIdx.x;
    int b0 = blockIdx.x * 8;
    int it = tid >> 5, o = tid & 31;
    float acc0 = 0.f, acc1 = 0.f;
    const __half* h1f = g_h1[1];          // final h1 (step 6 wrote dst=1)
#pragma unroll 1
    for (int cb = 0; cb < 8; cb++) {
        __syncthreads();
        for (int u = tid; u < 8 * 1344; u += 256) {
            int i2 = u / 1344, kk = u % 1344;
            shh[u] = __half2float(h1f[(size_t)(b0 + i2) * 10752 + cb * 1344 + kk]);
        }
        __syncthreads();
        const float* wp = g_fcwT + (size_t)cb * 1344 * 64 + o * 2;
        const float* hp = shh + it * 1344;
#pragma unroll 4
        for (int kk = 0; kk < 1344; kk++) {
            float hv = hp[kk];
            float2 w2 = __ldg((const float2*)(wp + (size_t)kk * 64));
            acc0 = fmaf(hv, w2.x, acc0);
            acc1 = fmaf(hv, w2.y, acc1);
        }
    }
    out[(size_t)(b0 + it) * 128 + o] = fmaxf(acc0 + fc1_b[o], 0.f);
    out[(size_t)(b0 + it) * 128 + o + 32] = fmaxf(acc1 + fc1_b[o + 32], 0.f);
}

// ---------------- exfc head: out[:, 64:128] ----------------
__global__ void k_exfc(const float* __restrict__ x_ex, const float* __restrict__ w,
                       const float* __restrict__ bias, float* __restrict__ out) {
    int idx = blockIdx.x * blockDim.x + threadIdx.x;
    if (idx >= BATCH * 64) return;
    int b = idx >> 6, o = idx & 63;
    float acc = bias[o];
#pragma unroll
    for (int k = 0; k < 24; k++) acc += x_ex[b * 24 + k] * __ldg(&w[o * 24 + k]);
    out[(size_t)b * 128 + 64 + o] = fmaxf(acc, 0.f);
}

// ---------------- launch ----------------
extern "C" void kernel_launch(void* const* d_in, const int* in_sizes, int n_in,
                              void* d_out, int out_size) {
    const float* input  = (const float*)d_in[0];
    const float* x_ex   = (const float*)d_in[1];
    const float* Wx0    = (const float*)d_in[2];
    const float* bx0    = (const float*)d_in[3];
    const float* Wh0    = (const float*)d_in[4];
    const float* Wc0    = (const float*)d_in[5];
    const float* Wx1    = (const float*)d_in[6];
    const float* bx1    = (const float*)d_in[7];
    const float* Wh1    = (const float*)d_in[8];
    const float* Wc1    = (const float*)d_in[9];
    const float* fc1_w  = (const float*)d_in[10];
    const float* fc1_b  = (const float*)d_in[11];
    const float* exfc_w = (const float*)d_in[12];
    const float* exfc_b = (const float*)d_in[13];
    float* out = (float*)d_out;

    (void)in_sizes; (void)n_in; (void)out_size;

    const int smem1 = P1HALVES * 2 + 2 * 16 * WBUF_N * 2;   // ~61.8 KB
    cudaFuncSetAttribute(k_cell1tc, cudaFuncAttributeMaxDynamicSharedMemorySize, smem1);

    k_zero<<<4096, 256>>>();
    k_gx0<<<BATCH, 256>>>(input, Wx0, bx0);
    k_wt<<<(10752 * 64 + 255) / 256, 256>>>(fc1_w);
    k_wtg<<<(HC0 * HC0 * 9 * 8 + 255) / 256, 256>>>(Wh0);
    k_w1h<<<(NCHUNK * 16 * 256 + 255) / 256, 256>>>(Wx1, Wh1);

    for (int s = 0; s < 7; s++) {
        k_cell0<<<BATCH, 224, HC0 * SPLANE * (int)sizeof(float)>>>(Wc0, s);
        k_cell1tc<<<BATCH, 512, smem1>>>(bx1, Wc1, s);
    }

    k_fc<<<BATCH / 8, 256>>>(fc1_b, out);
    k_exfc<<<(BATCH * 64 + 255) / 256, 256>>>(x_ex, exfc_w, exfc_b, out);
}

// round 11
// speedup vs baseline: 3.2535x; 1.2391x over previous
#include <cuda_runtime.h>
#include <cuda_fp16.h>
#include <math.h>

typedef unsigned long long ull;
typedef unsigned int uint;

#define BATCH 2048
#define HGT 7
#define WID 24
#define PIX 168            // 7*24
#define C0IN 2
#define HC0 32
#define HC1 64

// tensor-core geometry
#define P1ROW 26           // padded cols (24 + halo)
#define P1CH 96            // cell1 plane channels (32 h0 + 64 h1)
#define P1HALVES (9*P1ROW*P1CH)     // 22464 halves = 44928 B
#define WBUF_N 264         // cell1 weight SMEM row stride (256 + 8)
#define NCH1 54            // cell1: 9 taps * 6 ic16-chunks

#define P0HALVES (9*P1ROW*HC0)      // 7488 halves = 14976 B
#define W0ROW 136          // cell0 weight SMEM row stride (128 + 8)
#define NCH0 18            // cell0: 9 taps * 2 ic16-chunks

// ---------------- scratch ----------------
__device__ float  g_gx0[(size_t)BATCH * PIX * 128];     // [item][pix][hc*4+g], bias included
__device__ __half g_h0f[2][(size_t)BATCH * PIX * HC0];  // [item][pix][hc] fp16
__device__ float  g_c0[(size_t)BATCH * PIX * HC0];      // fp32
__device__ __half g_h1[2][(size_t)BATCH * PIX * HC1];   // [item][pix][hc] fp16
__device__ float  g_c1[(size_t)BATCH * PIX * HC1];      // fp32
__device__ float  g_fcwT[10752 * 64];
__device__ __align__(16) __half g_w0h[NCH0 * 16 * 128]; // [chunk][k16][n=hc*4+g]
__device__ __align__(16) __half g_w1h[NCH1 * 16 * 256]; // [chunk][k16][n=hc*4+g]

// ---------------- helpers ----------------
__device__ __forceinline__ float sigf(float x) { return 1.f / (1.f + expf(-x)); }
__device__ __forceinline__ uint smem_u32(const void* p) {
    uint a;
    asm("{ .reg .u64 t; cvta.to.shared.u64 t, %1; cvt.u32.u64 %0, t; }" : "=r"(a) : "l"(p));
    return a;
}

// ---------------- init ----------------
__global__ void k_zero() {
    size_t stride = (size_t)gridDim.x * blockDim.x;
    size_t gid = (size_t)blockIdx.x * blockDim.x + threadIdx.x;
    const size_t N0 = (size_t)BATCH * PIX * HC0;
    const size_t N1 = (size_t)BATCH * PIX * HC1;
    for (size_t i = gid; i < N0; i += stride) g_c0[i] = 0.f;
    for (size_t i = gid; i < N1; i += stride) g_c1[i] = 0.f;
    uint* h0z = (uint*)g_h0f[0];
    for (size_t i = gid; i < N0 / 2; i += stride) h0z[i] = 0u;
    uint* h1z = (uint*)g_h1[0];
    for (size_t i = gid; i < N1 / 2; i += stride) h1z[i] = 0u;
}

// ---------------- weight transforms ----------------
__global__ void k_w0h(const float* __restrict__ Wh0) {
    int idx = blockIdx.x * blockDim.x + threadIdx.x;
    if (idx >= NCH0 * 16 * 128) return;
    int chunk = idx / 2048, rem = idx % 2048;
    int k = rem / 128, n = rem % 128;
    int tap = chunk >> 1, icc = chunk & 1;
    int ic = icc * 16 + k;
    int hc = n >> 2, g = n & 3;
    g_w0h[idx] = __float2half(Wh0[((g * HC0 + hc) * HC0 + ic) * 9 + tap]);
}

__global__ void k_w1h(const float* __restrict__ Wx1, const float* __restrict__ Wh1) {
    int idx = blockIdx.x * blockDim.x + threadIdx.x;
    if (idx >= NCH1 * 16 * 256) return;
    int chunk = idx / 4096, rem = idx % 4096;
    int k = rem / 256, n = rem % 256;
    int tap = chunk / 6, icc = chunk % 6;
    int ic = icc * 16 + k;
    int hc = n / 4, g = n % 4;
    float v = (ic < HC0) ? Wx1[((g * HC1 + hc) * HC0 + ic) * 9 + tap]
                         : Wh1[((g * HC1 + hc) * HC1 + (ic - HC0)) * 9 + tap];
    g_w1h[idx] = __float2half(v);
}

// ---------------- gx0 = conv(input, Wx0) + bx0, layout [pix][hc*4+g] ----------------
#define SROW0 28
#define SPLANE0 (9*SROW0)
__global__ void k_gx0(const float* __restrict__ input, const float* __restrict__ Wx0,
                      const float* __restrict__ bx0) {
    __shared__ float sin_[C0IN * SPLANE0];
    int b = blockIdx.x, tid = threadIdx.x;
    for (int i = tid; i < C0IN * SPLANE0; i += blockDim.x) sin_[i] = 0.f;
    __syncthreads();
    for (int u = tid; u < C0IN * PIX; u += blockDim.x) {
        int ic = u / PIX, pix = u % PIX, y = pix / WID, x = pix % WID;
        sin_[ic * SPLANE0 + (y + 1) * SROW0 + (x + 1)] = input[(size_t)b * C0IN * PIX + u];
    }
    __syncthreads();
    for (int u = tid; u < 128 * PIX; u += blockDim.x) {
        int oc = u / PIX, pix = u % PIX, y = pix / WID, x = pix % WID;
        float acc = bx0[oc];
#pragma unroll
        for (int ic = 0; ic < C0IN; ic++)
#pragma unroll
            for (int ky = 0; ky < 3; ky++)
#pragma unroll
                for (int kx = 0; kx < 3; kx++)
                    acc += sin_[ic * SPLANE0 + (y + ky) * SROW0 + (x + kx)] *
                           __ldg(&Wx0[oc * 18 + ic * 9 + ky * 3 + kx]);
        int g = oc >> 5, hc = oc & 31;
        g_gx0[(size_t)b * PIX * 128 + pix * 128 + hc * 4 + g] = acc;
    }
}

// ---------------- layer-0 cell step: tensor-core implicit GEMM ----------------
__global__ void __launch_bounds__(512, 1)
k_cell0tc(const float* __restrict__ Wc0, int s) {
    __shared__ __align__(16) __half plane[P0HALVES];          // [9][26][32]
    __shared__ __align__(16) __half wbuf[2 * 16 * W0ROW];
    int b = blockIdx.x, tid = threadIdx.x;
    int src = s & 1, dst = src ^ 1;
    int lane = tid & 31, warp = tid >> 5;
    int mg = warp >> 2, ng = warp & 3;

    // ---- zero + fill plane from h0 fp16 [pix][32] ----
    uint4 z4; z4.x = z4.y = z4.z = z4.w = 0u;
    for (int i = tid; i < P0HALVES / 8; i += 512) ((uint4*)plane)[i] = z4;
    __syncthreads();
    const __half* h0s = g_h0f[src] + (size_t)b * PIX * HC0;
    for (int u = tid; u < PIX * 4; u += 512) {
        int pix = u >> 2, seg = u & 3;
        int y = pix / WID, x = pix % WID;
        uint4 v = *(const uint4*)(h0s + pix * HC0 + seg * 8);
        *(uint4*)(plane + ((y + 1) * P1ROW + (x + 1)) * HC0 + seg * 8) = v;
    }
    // ---- stage w0 chunk 0 (2048 halves; 512 x uint2) ----
    {
        uint2 v = *(const uint2*)(g_w0h + tid * 4);
        *(uint2*)(wbuf + (tid >> 5) * W0ROW + (tid & 31) * 4) = v;
    }
    __syncthreads();

    uint plU = smem_u32(plane);
    uint wbU = smem_u32(wbuf);

    int base26[3];
#pragma unroll
    for (int mt = 0; mt < 3; mt++) {
        int p = (mg * 3 + mt) * 16 + (lane & 15);
        if (p > 167) p = 167;
        base26[mt] = (p / WID + 1) * P1ROW + (p % WID + 1);
    }
    uint ahi = (uint)((lane >> 4) * 16);
    int bk = lane & 15;

    float d0[3][4][4];
#pragma unroll
    for (int mt = 0; mt < 3; mt++)
#pragma unroll
        for (int j = 0; j < 4; j++)
#pragma unroll
            for (int q = 0; q < 4; q++) d0[mt][j][q] = 0.f;

#pragma unroll 1
    for (int c = 0; c < NCH0; c++) {
        if (c + 1 < NCH0) {
            uint2 v = *(const uint2*)(g_w0h + (c + 1) * 2048 + tid * 4);
            *(uint2*)(wbuf + ((c + 1) & 1) * (16 * W0ROW) + (tid >> 5) * W0ROW +
                      (tid & 31) * 4) = v;
        }
        int tap = c >> 1, icc = c & 1;
        int tapoff = (tap / 3 - 1) * P1ROW + (tap % 3 - 1);
        uint wU = wbU + (uint)((c & 1) * (16 * W0ROW * 2));

        uint a[3][4];
#pragma unroll
        for (int mt = 0; mt < 3; mt++) {
            uint aaddr = plU + (uint)((base26[mt] + tapoff) * (HC0 * 2)) +
                         (uint)(icc * 32) + ahi;
            asm volatile("ldmatrix.sync.aligned.m8n8.x4.shared.b16 {%0,%1,%2,%3}, [%4];"
                         : "=r"(a[mt][0]), "=r"(a[mt][1]), "=r"(a[mt][2]), "=r"(a[mt][3])
                         : "r"(aaddr));
        }
#pragma unroll
        for (int np = 0; np < 2; np++) {
            uint baddr = wU + (uint)(bk * W0ROW * 2) +
                         (uint)(((lane >> 4) * 8 + ng * 32 + np * 16) * 2);
            uint b0, b1, b2, b3;
            asm volatile("ldmatrix.sync.aligned.m8n8.x4.trans.shared.b16 {%0,%1,%2,%3}, [%4];"
                         : "=r"(b0), "=r"(b1), "=r"(b2), "=r"(b3) : "r"(baddr));
#pragma unroll
            for (int mt = 0; mt < 3; mt++) {
                asm volatile("mma.sync.aligned.m16n8k16.row.col.f32.f16.f16.f32 "
                             "{%0,%1,%2,%3}, {%4,%5,%6,%7}, {%8,%9}, {%0,%1,%2,%3};"
                             : "+f"(d0[mt][2 * np][0]), "+f"(d0[mt][2 * np][1]),
                               "+f"(d0[mt][2 * np][2]), "+f"(d0[mt][2 * np][3])
                             : "r"(a[mt][0]), "r"(a[mt][1]), "r"(a[mt][2]), "r"(a[mt][3]),
                               "r"(b0), "r"(b1));
                asm volatile("mma.sync.aligned.m16n8k16.row.col.f32.f16.f16.f32 "
                             "{%0,%1,%2,%3}, {%4,%5,%6,%7}, {%8,%9}, {%0,%1,%2,%3};"
                             : "+f"(d0[mt][2 * np + 1][0]), "+f"(d0[mt][2 * np + 1][1]),
                               "+f"(d0[mt][2 * np + 1][2]), "+f"(d0[mt][2 * np + 1][3])
                             : "r"(a[mt][0]), "r"(a[mt][1]), "r"(a[mt][2]), "r"(a[mt][3]),
                               "r"(b2), "r"(b3));
            }
        }
        __syncthreads();
    }

    // ---- epilogue: gates -> (c0, h0 fp16) ----
    float* c0f = g_c0 + (size_t)b * PIX * HC0;
    __half* h0d = g_h0f[dst] + (size_t)b * PIX * HC0;
    const float* gx0p = g_gx0 + (size_t)b * PIX * 128;
    int t = lane & 3, r = lane >> 2, odd = t & 1;
#pragma unroll
    for (int mt = 0; mt < 3; mt++) {
        int tile = mg * 3 + mt;
#pragma unroll
        for (int j = 0; j < 4; j++) {
            float v0 = d0[mt][j][0], v1 = d0[mt][j][1], v2 = d0[mt][j][2], v3 = d0[mt][j][3];
            float x0 = __shfl_xor_sync(0xffffffffu, v0, 1);
            float x1 = __shfl_xor_sync(0xffffffffu, v1, 1);
            float x2 = __shfl_xor_sync(0xffffffffu, v2, 1);
            float x3 = __shfl_xor_sync(0xffffffffu, v3, 1);
            int pixel = tile * 16 + r + odd * 8;
            int hc = ng * 8 + j * 2 + (t >> 1);
            float gi = odd ? x2 : v0;
            float gf = odd ? x3 : v1;
            float gc = odd ? v2 : x0;
            float go = odd ? v3 : x1;
            if (pixel < PIX) {
                float4 gx = __ldg((const float4*)(gx0p + pixel * 128 + hc * 4));
                gi += gx.x; gf += gx.y; gc += gx.z; go += gx.w;
                float cold = c0f[pixel * HC0 + hc];
                float w0 = __ldg(&Wc0[hc * PIX + pixel]);
                float w1 = __ldg(&Wc0[HC0 * PIX + hc * PIX + pixel]);
                float w2 = __ldg(&Wc0[2 * HC0 * PIX + hc * PIX + pixel]);
                float ci = sigf(gi + cold * w0);
                float cf = sigf(gf + cold * w1);
                float cc = cf * cold + ci * tanhf(gc);
                float co = sigf(go + cc * w2);
                c0f[pixel * HC0 + hc] = cc;
                h0d[pixel * HC0 + hc] = __float2half(co * tanhf(cc));
            }
        }
    }
}

// ---------------- layer-1 cell step: tensor-core implicit GEMM (R7-proven) ----------------
__global__ void __launch_bounds__(512, 1)
k_cell1tc(const float* __restrict__ bx1, const float* __restrict__ Wc1, int s) {
    extern __shared__ __align__(16) char smraw[];
    __half* plane = (__half*)smraw;                              // P1HALVES
    __half* wbuf = (__half*)(smraw + P1HALVES * 2);              // 2 * 16 * WBUF_N
    int b = blockIdx.x, tid = threadIdx.x;
    int src = s & 1, dst = src ^ 1;

    // ---- build fp16 halo plane [9][26][96]: ch 0-31 = h0_new, 32-95 = h1_old ----
    uint4 z4; z4.x = z4.y = z4.z = z4.w = 0u;
    for (int i = tid; i < P1HALVES / 8; i += 512) ((uint4*)plane)[i] = z4;
    __syncthreads();
    const __half* h0n = g_h0f[dst] + (size_t)b * PIX * HC0;      // fresh from cell0
    for (int u = tid; u < PIX * 4; u += 512) {
        int pix = u >> 2, seg = u & 3;
        int y = pix / WID, x = pix % WID;
        uint4 v = *(const uint4*)(h0n + pix * HC0 + seg * 8);
        *(uint4*)(plane + ((y + 1) * P1ROW + (x + 1)) * P1CH + seg * 8) = v;
    }
    const __half* h1s = g_h1[src] + (size_t)b * PIX * HC1;
    for (int u = tid; u < PIX * 8; u += 512) {
        int pix = u / 8, seg = u % 8;
        int y = pix / WID, x = pix % WID;
        uint4 v = *(const uint4*)(h1s + pix * HC1 + seg * 8);
        *(uint4*)(plane + ((y + 1) * P1ROW + (x + 1)) * P1CH + 32 + seg * 8) = v;
    }

    // ---- stage weight chunk 0 ----
    {
        uint4 v = *(const uint4*)(g_w1h + tid * 8);
        *(uint4*)(wbuf + (tid >> 5) * WBUF_N + (tid & 31) * 8) = v;
    }
    __syncthreads();

    uint planeU = smem_u32(plane);
    uint wbufU = smem_u32(wbuf);
    int lane = tid & 31, warp = tid >> 5;
    int mg = warp >> 2, ng = warp & 3;

    int base26[3];
#pragma unroll
    for (int mt = 0; mt < 3; mt++) {
        int p = (mg * 3 + mt) * 16 + (lane & 15);
        if (p > 167) p = 167;
        int y = p / WID, x = p % WID;
        base26[mt] = (y + 1) * P1ROW + (x + 1);
    }
    uint ahi = (uint)((lane >> 4) * 16);
    int bk = lane & 15;
    uint bsel = (uint)(((lane >> 4) * 8 + ng * 64) * 2);

    float d[3][8][4];
#pragma unroll
    for (int mt = 0; mt < 3; mt++)
#pragma unroll
        for (int j = 0; j < 8; j++)
#pragma unroll
            for (int q = 0; q < 4; q++) d[mt][j][q] = 0.f;

#pragma unroll 1
    for (int c = 0; c < NCH1; c++) {
        if (c + 1 < NCH1) {
            uint4 v = *(const uint4*)(g_w1h + (size_t)(c + 1) * 4096 + tid * 8);
            __half* wb = wbuf + ((c + 1) & 1) * (16 * WBUF_N);
            *(uint4*)(wb + (tid >> 5) * WBUF_N + (tid & 31) * 8) = v;
        }
        int tap = c / 6, icc = c % 6;
        int tapoff = (tap / 3 - 1) * P1ROW + (tap % 3 - 1);
        uint wU = wbufU + (uint)((c & 1) * (16 * WBUF_N * 2));

        uint a[3][4];
#pragma unroll
        for (int mt = 0; mt < 3; mt++) {
            uint aaddr = planeU + (uint)((base26[mt] + tapoff) * (P1CH * 2)) + (uint)(icc * 32) + ahi;
            asm volatile("ldmatrix.sync.aligned.m8n8.x4.shared.b16 {%0,%1,%2,%3}, [%4];"
                         : "=r"(a[mt][0]), "=r"(a[mt][1]), "=r"(a[mt][2]), "=r"(a[mt][3])
                         : "r"(aaddr));
        }
#pragma unroll
        for (int np = 0; np < 4; np++) {
            uint baddr = wU + (uint)(bk * WBUF_N * 2) + bsel + (uint)(np * 32);
            uint b0, b1, b2, b3;
            asm volatile("ldmatrix.sync.aligned.m8n8.x4.trans.shared.b16 {%0,%1,%2,%3}, [%4];"
                         : "=r"(b0), "=r"(b1), "=r"(b2), "=r"(b3) : "r"(baddr));
#pragma unroll
            for (int mt = 0; mt < 3; mt++) {
                asm volatile("mma.sync.aligned.m16n8k16.row.col.f32.f16.f16.f32 "
                             "{%0,%1,%2,%3}, {%4,%5,%6,%7}, {%8,%9}, {%0,%1,%2,%3};"
                             : "+f"(d[mt][2 * np][0]), "+f"(d[mt][2 * np][1]),
                               "+f"(d[mt][2 * np][2]), "+f"(d[mt][2 * np][3])
                             : "r"(a[mt][0]), "r"(a[mt][1]), "r"(a[mt][2]), "r"(a[mt][3]),
                               "r"(b0), "r"(b1));
                asm volatile("mma.sync.aligned.m16n8k16.row.col.f32.f16.f16.f32 "
                             "{%0,%1,%2,%3}, {%4,%5,%6,%7}, {%8,%9}, {%0,%1,%2,%3};"
                             : "+f"(d[mt][2 * np + 1][0]), "+f"(d[mt][2 * np + 1][1]),
                               "+f"(d[mt][2 * np + 1][2]), "+f"(d[mt][2 * np + 1][3])
                             : "r"(a[mt][0]), "r"(a[mt][1]), "r"(a[mt][2]), "r"(a[mt][3]),
                               "r"(b2), "r"(b3));
            }
        }
        __syncthreads();
    }

    // ---- epilogue: gather 4 gates per (pixel,hc) via bfly shuffle, LSTM pointwise ----
    float* c1f = g_c1 + (size_t)b * PIX * HC1;
    __half* h1d = g_h1[dst] + (size_t)b * PIX * HC1;
    int t = lane & 3, r = lane >> 2;
    int odd = t & 1;
#pragma unroll
    for (int mt = 0; mt < 3; mt++) {
        int tile = mg * 3 + mt;
#pragma unroll
        for (int j = 0; j < 8; j++) {
            float v0 = d[mt][j][0], v1 = d[mt][j][1], v2 = d[mt][j][2], v3 = d[mt][j][3];
            float x0 = __shfl_xor_sync(0xffffffffu, v0, 1);
            float x1 = __shfl_xor_sync(0xffffffffu, v1, 1);
            float x2 = __shfl_xor_sync(0xffffffffu, v2, 1);
            float x3 = __shfl_xor_sync(0xffffffffu, v3, 1);
            int pixel = tile * 16 + r + odd * 8;
            int hc = ng * 16 + j * 2 + (t >> 1);
            float gi = odd ? x2 : v0;
            float gf = odd ? x3 : v1;
            float gc = odd ? v2 : x0;
            float go = odd ? v3 : x1;
            if (pixel < PIX) {
                gi += __ldg(&bx1[hc]);
                gf += __ldg(&bx1[64 + hc]);
                gc += __ldg(&bx1[128 + hc]);
                go += __ldg(&bx1[192 + hc]);
                float cold = c1f[pixel * HC1 + hc];
                float w0 = __ldg(&Wc1[hc * PIX + pixel]);
                float w1 = __ldg(&Wc1[10752 + hc * PIX + pixel]);
                float w2 = __ldg(&Wc1[21504 + hc * PIX + pixel]);
                float ci = sigf(gi + cold * w0);
                float cf = sigf(gf + cold * w1);
                float cc = cf * cold + ci * tanhf(gc);
                float co = sigf(go + cc * w2);
                c1f[pixel * HC1 + hc] = cc;
                h1d[pixel * HC1 + hc] = __float2half(co * tanhf(cc));
            }
        }
    }
}

// ---------------- fc1 weight transpose: k follows [pix][ch] flatten ----------------
__global__ void k_wt(const float* __restrict__ fc1_w) {
    int idx = blockIdx.x * blockDim.x + threadIdx.x;
    if (idx >= 10752 * 64) return;
    int k = idx / 64, o = idx % 64;       // k = pix*64 + ch
    int pix = k / 64, ch = k % 64;
    g_fcwT[k * 64 + (o & 31) * 2 + (o >> 5)] = fc1_w[(size_t)o * 10752 + ch * PIX + pix];
}

// ---------------- fc1 head: out[:, 0:64] ----------------
__global__ void k_fc(const float* __restrict__ fc1_b, float* __restrict__ out) {
    __shared__ float shh[8 * 1344];
    int tid = threadIdx.x;
    int b0 = blockIdx.x * 8;
    int it = tid >> 5, o = tid & 31;
    float acc0 = 0.f, acc1 = 0.f;
    const __half* h1f = g_h1[1];          // final h1 (step 6 wrote dst=1)
#pragma unroll 1
    for (int cb = 0; cb < 8; cb++) {
        __syncthreads();
        for (int u = tid; u < 8 * 1344; u += 256) {
            int i2 = u / 1344, kk = u % 1344;
            shh[u] = __half2float(h1f[(size_t)(b0 + i2) * 10752 + cb * 1344 + kk]);
        }
        __syncthreads();
        const float* wp = g_fcwT + (size_t)cb * 1344 * 64 + o * 2;
        const float* hp = shh + it * 1344;
#pragma unroll 4
        for (int kk = 0; kk < 1344; kk++) {
            float hv = hp[kk];
            float2 w2 = __ldg((const float2*)(wp + (size_t)kk * 64));
            acc0 = fmaf(hv, w2.x, acc0);
            acc1 = fmaf(hv, w2.y, acc1);
        }
    }
    out[(size_t)(b0 + it) * 128 + o] = fmaxf(acc0 + fc1_b[o], 0.f);
    out[(size_t)(b0 + it) * 128 + o + 32] = fmaxf(acc1 + fc1_b[o + 32], 0.f);
}

// ---------------- exfc head: out[:, 64:128] ----------------
__global__ void k_exfc(const float* __restrict__ x_ex, const float* __restrict__ w,
                       const float* __restrict__ bias, float* __restrict__ out) {
    int idx = blockIdx.x * blockDim.x + threadIdx.x;
    if (idx >= BATCH * 64) return;
    int b = idx >> 6, o = idx & 63;
    float acc = bias[o];
#pragma unroll
    for (int k = 0; k < 24; k++) acc += x_ex[b * 24 + k] * __ldg(&w[o * 24 + k]);
    out[(size_t)b * 128 + 64 + o] = fmaxf(acc, 0.f);
}

// ---------------- launch ----------------
extern "C" void kernel_launch(void* const* d_in, const int* in_sizes, int n_in,
                              void* d_out, int out_size) {
    const float* input  = (const float*)d_in[0];
    const float* x_ex   = (const float*)d_in[1];
    const float* Wx0    = (const float*)d_in[2];
    const float* bx0    = (const float*)d_in[3];
    const float* Wh0    = (const float*)d_in[4];
    const float* Wc0    = (const float*)d_in[5];
    const float* Wx1    = (const float*)d_in[6];
    const float* bx1    = (const float*)d_in[7];
    const float* Wh1    = (const float*)d_in[8];
    const float* Wc1    = (const float*)d_in[9];
    const float* fc1_w  = (const float*)d_in[10];
    const float* fc1_b  = (const float*)d_in[11];
    const float* exfc_w = (const float*)d_in[12];
    const float* exfc_b = (const float*)d_in[13];
    float* out = (float*)d_out;

    (void)in_sizes; (void)n_in; (void)out_size;

    const int smem1 = P1HALVES * 2 + 2 * 16 * WBUF_N * 2;   // ~61.8 KB
    cudaFuncSetAttribute(k_cell1tc, cudaFuncAttributeMaxDynamicSharedMemorySize, smem1);

    k_zero<<<4096, 256>>>();
    k_gx0<<<BATCH, 256>>>(input, Wx0, bx0);
    k_wt<<<(10752 * 64 + 255) / 256, 256>>>(fc1_w);
    k_w0h<<<(NCH0 * 16 * 128 + 255) / 256, 256>>>(Wh0);
    k_w1h<<<(NCH1 * 16 * 256 + 255) / 256, 256>>>(Wx1, Wh1);

    for (int s = 0; s < 7; s++) {
        k_cell0tc<<<BATCH, 512>>>(Wc0, s);
        k_cell1tc<<<BATCH, 512, smem1>>>(bx1, Wc1, s);
    }

    k_fc<<<BATCH / 8, 256>>>(fc1_b, out);
    k_exfc<<<(BATCH * 64 + 255) / 256, 256>>>(x_ex, exfc_w, exfc_b, out);
}

// round 12
// speedup vs baseline: 3.8941x; 1.1969x over previous
#include <cuda_runtime.h>
#include <cuda_fp16.h>
#include <math.h>

typedef unsigned long long ull;
typedef unsigned int uint;

#define BATCH 2048
#define HGT 7
#define WID 24
#define PIX 168            // 7*24
#define C0IN 2
#define HC0 32
#define HC1 64

// tensor-core geometry
#define P1ROW 26           // padded cols (24 + halo)
#define P1CH 96            // cell1 plane channels (32 h0 + 64 h1)
#define P1HALVES (9*P1ROW*P1CH)     // 22464 halves = 44928 B
#define NCH1 54            // cell1: 9 taps * 6 ic16-chunks

#define P0HALVES (9*P1ROW*HC0)      // 7488 halves = 14976 B
#define NCH0 18            // cell0: 9 taps * 2 ic16-chunks

// ---------------- scratch ----------------
__device__ float  g_gx0[(size_t)BATCH * PIX * 128];     // [item][pix][hc*4+g], bias included
__device__ __half g_h0f[2][(size_t)BATCH * PIX * HC0];  // [item][pix][hc] fp16
__device__ float  g_c0[(size_t)BATCH * PIX * HC0];      // fp32
__device__ __half g_h1[2][(size_t)BATCH * PIX * HC1];   // [item][pix][hc] fp16
__device__ float  g_c1[(size_t)BATCH * PIX * HC1];      // fp32
__device__ float  g_fcwT[10752 * 64];
__device__ __align__(16) __half g_w0h[NCH0 * 16 * 128]; // [chunk][k16][n=hc*4+g]
__device__ __align__(16) __half g_w1h[NCH1 * 16 * 256]; // [chunk][k16][n=hc*4+g]
// mma B-fragment layouts: [chunk][n8pair][lane][4 x b32]; pair covers tiles (2pp, 2pp+1)
__device__ __align__(16) uint g_w0f[NCH0 * 8 * 32 * 4];   //  73728 B
__device__ __align__(16) uint g_w1f[NCH1 * 16 * 32 * 4];  // 442368 B

// ---------------- helpers ----------------
__device__ __forceinline__ float sigf(float x) { return 1.f / (1.f + expf(-x)); }
__device__ __forceinline__ uint smem_u32(const void* p) {
    uint a;
    asm("{ .reg .u64 t; cvta.to.shared.u64 t, %1; cvt.u32.u64 %0, t; }" : "=r"(a) : "l"(p));
    return a;
}

// ---------------- init ----------------
__global__ void k_zero() {
    size_t stride = (size_t)gridDim.x * blockDim.x;
    size_t gid = (size_t)blockIdx.x * blockDim.x + threadIdx.x;
    const size_t N0 = (size_t)BATCH * PIX * HC0;
    const size_t N1 = (size_t)BATCH * PIX * HC1;
    for (size_t i = gid; i < N0; i += stride) g_c0[i] = 0.f;
    for (size_t i = gid; i < N1; i += stride) g_c1[i] = 0.f;
    uint* h0z = (uint*)g_h0f[0];
    for (size_t i = gid; i < N0 / 2; i += stride) h0z[i] = 0u;
    uint* h1z = (uint*)g_h1[0];
    for (size_t i = gid; i < N1 / 2; i += stride) h1z[i] = 0u;
}

// ---------------- weight transforms (k-major staging layout) ----------------
__global__ void k_w0h(const float* __restrict__ Wh0) {
    int idx = blockIdx.x * blockDim.x + threadIdx.x;
    if (idx >= NCH0 * 16 * 128) return;
    int chunk = idx / 2048, rem = idx % 2048;
    int k = rem / 128, n = rem % 128;
    int tap = chunk >> 1, icc = chunk & 1;
    int ic = icc * 16 + k;
    int hc = n >> 2, g = n & 3;
    g_w0h[idx] = __float2half(Wh0[((g * HC0 + hc) * HC0 + ic) * 9 + tap]);
}

__global__ void k_w1h(const float* __restrict__ Wx1, const float* __restrict__ Wh1) {
    int idx = blockIdx.x * blockDim.x + threadIdx.x;
    if (idx >= NCH1 * 16 * 256) return;
    int chunk = idx / 4096, rem = idx % 4096;
    int k = rem / 256, n = rem % 256;
    int tap = chunk / 6, icc = chunk % 6;
    int ic = icc * 16 + k;
    int hc = n / 4, g = n % 4;
    float v = (ic < HC0) ? Wx1[((g * HC1 + hc) * HC0 + ic) * 9 + tap]
                         : Wh1[((g * HC1 + hc) * HC1 + (ic - HC0)) * 9 + tap];
    g_w1h[idx] = __float2half(v);
}

// ---------------- fragmentizers: k-major -> mma B-fragment order ----------------
// frag uint at ((c*NPAIR + pp)*32 + l)*4 + q:
//   tile tt = pp*2 + (q>>1), reg r = q&1
//   value = {W[c][k0][n], W[c][k0+1][n]},  k0 = (l&3)*2 + r*8,  n = tt*8 + (l>>2)
__global__ void k_w0f() {
    int idx = blockIdx.x * blockDim.x + threadIdx.x;
    if (idx >= NCH0 * 8 * 32 * 4) return;
    int q = idx & 3, l = (idx >> 2) & 31, pp = (idx >> 7) & 7, c = idx >> 10;
    int tt = pp * 2 + (q >> 1), r = q & 1;
    int k0 = (l & 3) * 2 + r * 8, n = tt * 8 + (l >> 2);
    __half h0 = g_w0h[c * 2048 + k0 * 128 + n];
    __half h1 = g_w0h[c * 2048 + (k0 + 1) * 128 + n];
    ((__half2*)g_w0f)[idx] = __halves2half2(h0, h1);
}

__global__ void k_w1f() {
    int idx = blockIdx.x * blockDim.x + threadIdx.x;
    if (idx >= NCH1 * 16 * 32 * 4) return;
    int q = idx & 3, l = (idx >> 2) & 31, pp = (idx >> 7) & 15, c = idx >> 11;
    int tt = pp * 2 + (q >> 1), r = q & 1;
    int k0 = (l & 3) * 2 + r * 8, n = tt * 8 + (l >> 2);
    __half h0 = g_w1h[c * 4096 + k0 * 256 + n];
    __half h1 = g_w1h[c * 4096 + (k0 + 1) * 256 + n];
    ((__half2*)g_w1f)[idx] = __halves2half2(h0, h1);
}

// ---------------- gx0 = conv(input, Wx0) + bx0, layout [pix][hc*4+g] ----------------
#define SROW0 28
#define SPLANE0 (9*SROW0)
__global__ void k_gx0(const float* __restrict__ input, const float* __restrict__ Wx0,
                      const float* __restrict__ bx0) {
    __shared__ float sin_[C0IN * SPLANE0];
    int b = blockIdx.x, tid = threadIdx.x;
    for (int i = tid; i < C0IN * SPLANE0; i += blockDim.x) sin_[i] = 0.f;
    __syncthreads();
    for (int u = tid; u < C0IN * PIX; u += blockDim.x) {
        int ic = u / PIX, pix = u % PIX, y = pix / WID, x = pix % WID;
        sin_[ic * SPLANE0 + (y + 1) * SROW0 + (x + 1)] = input[(size_t)b * C0IN * PIX + u];
    }
    __syncthreads();
    for (int u = tid; u < 128 * PIX; u += blockDim.x) {
        int oc = u / PIX, pix = u % PIX, y = pix / WID, x = pix % WID;
        float acc = bx0[oc];
#pragma unroll
        for (int ic = 0; ic < C0IN; ic++)
#pragma unroll
            for (int ky = 0; ky < 3; ky++)
#pragma unroll
                for (int kx = 0; kx < 3; kx++)
                    acc += sin_[ic * SPLANE0 + (y + ky) * SROW0 + (x + kx)] *
                           __ldg(&Wx0[oc * 18 + ic * 9 + ky * 3 + kx]);
        int g = oc >> 5, hc = oc & 31;
        g_gx0[(size_t)b * PIX * 128 + pix * 128 + hc * 4 + g] = acc;
    }
}

// ---------------- layer-0 cell step: HMMA, sync-free K-loop ----------------
__global__ void __launch_bounds__(512, 1)
k_cell0tc(const float* __restrict__ Wc0, int s) {
    __shared__ __align__(16) __half plane[P0HALVES];          // [9][26][32]
    int b = blockIdx.x, tid = threadIdx.x;
    int src = s & 1, dst = src ^ 1;
    int lane = tid & 31, warp = tid >> 5;
    int mg = warp >> 2, ng = warp & 3;

    // ---- zero + fill plane from h0 fp16 [pix][32] ----
    uint4 z4; z4.x = z4.y = z4.z = z4.w = 0u;
    for (int i = tid; i < P0HALVES / 8; i += 512) ((uint4*)plane)[i] = z4;
    __syncthreads();
    const __half* h0s = g_h0f[src] + (size_t)b * PIX * HC0;
    for (int u = tid; u < PIX * 4; u += 512) {
        int pix = u >> 2, seg = u & 3;
        int y = pix / WID, x = pix % WID;
        uint4 v = *(const uint4*)(h0s + pix * HC0 + seg * 8);
        *(uint4*)(plane + ((y + 1) * P1ROW + (x + 1)) * HC0 + seg * 8) = v;
    }
    __syncthreads();

    uint plU = smem_u32(plane);

    int base26[3];
#pragma unroll
    for (int mt = 0; mt < 3; mt++) {
        int p = (mg * 3 + mt) * 16 + (lane & 15);
        if (p > 167) p = 167;
        base26[mt] = (p / WID + 1) * P1ROW + (p % WID + 1);
    }
    uint ahi = (uint)((lane >> 4) * 16);

    float d0[3][4][4];
#pragma unroll
    for (int mt = 0; mt < 3; mt++)
#pragma unroll
        for (int j = 0; j < 4; j++)
#pragma unroll
            for (int q = 0; q < 4; q++) d0[mt][j][q] = 0.f;

#pragma unroll 1
    for (int c = 0; c < NCH0; c++) {
        int tap = c >> 1, icc = c & 1;
        int tapoff = (tap / 3 - 1) * P1ROW + (tap % 3 - 1);

        uint a[3][4];
#pragma unroll
        for (int mt = 0; mt < 3; mt++) {
            uint aaddr = plU + (uint)((base26[mt] + tapoff) * (HC0 * 2)) +
                         (uint)(icc * 32) + ahi;
            asm volatile("ldmatrix.sync.aligned.m8n8.x4.shared.b16 {%0,%1,%2,%3}, [%4];"
                         : "=r"(a[mt][0]), "=r"(a[mt][1]), "=r"(a[mt][2]), "=r"(a[mt][3])
                         : "r"(aaddr));
        }
        const uint4* fp = (const uint4*)g_w0f + (size_t)(c * 8 + ng * 2) * 32 + lane;
#pragma unroll
        for (int j = 0; j < 2; j++) {
            uint4 v = __ldg(fp + j * 32);
#pragma unroll
            for (int mt = 0; mt < 3; mt++) {
                asm volatile("mma.sync.aligned.m16n8k16.row.col.f32.f16.f16.f32 "
                             "{%0,%1,%2,%3}, {%4,%5,%6,%7}, {%8,%9}, {%0,%1,%2,%3};"
                             : "+f"(d0[mt][2 * j][0]), "+f"(d0[mt][2 * j][1]),
                               "+f"(d0[mt][2 * j][2]), "+f"(d0[mt][2 * j][3])
                             : "r"(a[mt][0]), "r"(a[mt][1]), "r"(a[mt][2]), "r"(a[mt][3]),
                               "r"(v.x), "r"(v.y));
                asm volatile("mma.sync.aligned.m16n8k16.row.col.f32.f16.f16.f32 "
                             "{%0,%1,%2,%3}, {%4,%5,%6,%7}, {%8,%9}, {%0,%1,%2,%3};"
                             : "+f"(d0[mt][2 * j + 1][0]), "+f"(d0[mt][2 * j + 1][1]),
                               "+f"(d0[mt][2 * j + 1][2]), "+f"(d0[mt][2 * j + 1][3])
                             : "r"(a[mt][0]), "r"(a[mt][1]), "r"(a[mt][2]), "r"(a[mt][3]),
                               "r"(v.z), "r"(v.w));
            }
        }
    }

    // ---- epilogue: gates -> (c0, h0 fp16) ----
    float* c0f = g_c0 + (size_t)b * PIX * HC0;
    __half* h0d = g_h0f[dst] + (size_t)b * PIX * HC0;
    const float* gx0p = g_gx0 + (size_t)b * PIX * 128;
    int t = lane & 3, r = lane >> 2, odd = t & 1;
#pragma unroll
    for (int mt = 0; mt < 3; mt++) {
        int tile = mg * 3 + mt;
#pragma unroll
        for (int j = 0; j < 4; j++) {
            float v0 = d0[mt][j][0], v1 = d0[mt][j][1], v2 = d0[mt][j][2], v3 = d0[mt][j][3];
            float x0 = __shfl_xor_sync(0xffffffffu, v0, 1);
            float x1 = __shfl_xor_sync(0xffffffffu, v1, 1);
            float x2 = __shfl_xor_sync(0xffffffffu, v2, 1);
            float x3 = __shfl_xor_sync(0xffffffffu, v3, 1);
            int pixel = tile * 16 + r + odd * 8;
            int hc = ng * 8 + j * 2 + (t >> 1);
            float gi = odd ? x2 : v0;
            float gf = odd ? x3 : v1;
            float gc = odd ? v2 : x0;
            float go = odd ? v3 : x1;
            if (pixel < PIX) {
                float4 gx = __ldg((const float4*)(gx0p + pixel * 128 + hc * 4));
                gi += gx.x; gf += gx.y; gc += gx.z; go += gx.w;
                float cold = c0f[pixel * HC0 + hc];
                float w0 = __ldg(&Wc0[hc * PIX + pixel]);
                float w1 = __ldg(&Wc0[HC0 * PIX + hc * PIX + pixel]);
                float w2 = __ldg(&Wc0[2 * HC0 * PIX + hc * PIX + pixel]);
                float ci = sigf(gi + cold * w0);
                float cf = sigf(gf + cold * w1);
                float cc = cf * cold + ci * tanhf(gc);
                float co = sigf(go + cc * w2);
                c0f[pixel * HC0 + hc] = cc;
                h0d[pixel * HC0 + hc] = __float2half(co * tanhf(cc));
            }
        }
    }
}

// ---------------- layer-1 cell step: HMMA, sync-free K-loop ----------------
__global__ void __launch_bounds__(512, 1)
k_cell1tc(const float* __restrict__ bx1, const float* __restrict__ Wc1, int s) {
    __shared__ __align__(16) __half plane[P1HALVES];             // [9][26][96]
    int b = blockIdx.x, tid = threadIdx.x;
    int src = s & 1, dst = src ^ 1;

    // ---- build fp16 halo plane: ch 0-31 = h0_new, 32-95 = h1_old ----
    uint4 z4; z4.x = z4.y = z4.z = z4.w = 0u;
    for (int i = tid; i < P1HALVES / 8; i += 512) ((uint4*)plane)[i] = z4;
    __syncthreads();
    const __half* h0n = g_h0f[dst] + (size_t)b * PIX * HC0;      // fresh from cell0
    for (int u = tid; u < PIX * 4; u += 512) {
        int pix = u >> 2, seg = u & 3;
        int y = pix / WID, x = pix % WID;
        uint4 v = *(const uint4*)(h0n + pix * HC0 + seg * 8);
        *(uint4*)(plane + ((y + 1) * P1ROW + (x + 1)) * P1CH + seg * 8) = v;
    }
    const __half* h1s = g_h1[src] + (size_t)b * PIX * HC1;
    for (int u = tid; u < PIX * 8; u += 512) {
        int pix = u / 8, seg = u % 8;
        int y = pix / WID, x = pix % WID;
        uint4 v = *(const uint4*)(h1s + pix * HC1 + seg * 8);
        *(uint4*)(plane + ((y + 1) * P1ROW + (x + 1)) * P1CH + 32 + seg * 8) = v;
    }
    __syncthreads();

    uint planeU = smem_u32(plane);
    int lane = tid & 31, warp = tid >> 5;
    int mg = warp >> 2, ng = warp & 3;

    int base26[3];
#pragma unroll
    for (int mt = 0; mt < 3; mt++) {
        int p = (mg * 3 + mt) * 16 + (lane & 15);
        if (p > 167) p = 167;
        int y = p / WID, x = p % WID;
        base26[mt] = (y + 1) * P1ROW + (x + 1);
    }
    uint ahi = (uint)((lane >> 4) * 16);

    float d[3][8][4];
#pragma unroll
    for (int mt = 0; mt < 3; mt++)
#pragma unroll
        for (int j = 0; j < 8; j++)
#pragma unroll
            for (int q = 0; q < 4; q++) d[mt][j][q] = 0.f;

#pragma unroll 1
    for (int c = 0; c < NCH1; c++) {
        int tap = c / 6, icc = c % 6;
        int tapoff = (tap / 3 - 1) * P1ROW + (tap % 3 - 1);

        uint a[3][4];
#pragma unroll
        for (int mt = 0; mt < 3; mt++) {
            uint aaddr = planeU + (uint)((base26[mt] + tapoff) * (P1CH * 2)) + (uint)(icc * 32) + ahi;
            asm volatile("ldmatrix.sync.aligned.m8n8.x4.shared.b16 {%0,%1,%2,%3}, [%4];"
                         : "=r"(a[mt][0]), "=r"(a[mt][1]), "=r"(a[mt][2]), "=r"(a[mt][3])
                         : "r"(aaddr));
        }
        const uint4* fp = (const uint4*)g_w1f + (size_t)(c * 16 + ng * 4) * 32 + lane;
#pragma unroll
        for (int j = 0; j < 4; j++) {
            uint4 v = __ldg(fp + j * 32);
#pragma unroll
            for (int mt = 0; mt < 3; mt++) {
                asm volatile("mma.sync.aligned.m16n8k16.row.col.f32.f16.f16.f32 "
                             "{%0,%1,%2,%3}, {%4,%5,%6,%7}, {%8,%9}, {%0,%1,%2,%3};"
                             : "+f"(d[mt][2 * j][0]), "+f"(d[mt][2 * j][1]),
                               "+f"(d[mt][2 * j][2]), "+f"(d[mt][2 * j][3])
                             : "r"(a[mt][0]), "r"(a[mt][1]), "r"(a[mt][2]), "r"(a[mt][3]),
                               "r"(v.x), "r"(v.y));
                asm volatile("mma.sync.aligned.m16n8k16.row.col.f32.f16.f16.f32 "
                             "{%0,%1,%2,%3}, {%4,%5,%6,%7}, {%8,%9}, {%0,%1,%2,%3};"
                             : "+f"(d[mt][2 * j + 1][0]), "+f"(d[mt][2 * j + 1][1]),
                               "+f"(d[mt][2 * j + 1][2]), "+f"(d[mt][2 * j + 1][3])
                             : "r"(a[mt][0]), "r"(a[mt][1]), "r"(a[mt][2]), "r"(a[mt][3]),
                               "r"(v.z), "r"(v.w));
            }
        }
    }

    // ---- epilogue: gather 4 gates per (pixel,hc) via bfly shuffle, LSTM pointwise ----
    float* c1f = g_c1 + (size_t)b * PIX * HC1;
    __half* h1d = g_h1[dst] + (size_t)b * PIX * HC1;
    int t = lane & 3, r = lane >> 2;
    int odd = t & 1;
#pragma unroll
    for (int mt = 0; mt < 3; mt++) {
        int tile = mg * 3 + mt;
#pragma unroll
        for (int j = 0; j < 8; j++) {
            float v0 = d[mt][j][0], v1 = d[mt][j][1], v2 = d[mt][j][2], v3 = d[mt][j][3];
            float x0 = __shfl_xor_sync(0xffffffffu, v0, 1);
            float x1 = __shfl_xor_sync(0xffffffffu, v1, 1);
            float x2 = __shfl_xor_sync(0xffffffffu, v2, 1);
            float x3 = __shfl_xor_sync(0xffffffffu, v3, 1);
            int pixel = tile * 16 + r + odd * 8;
            int hc = ng * 16 + j * 2 + (t >> 1);
            float gi = odd ? x2 : v0;
            float gf = odd ? x3 : v1;
            float gc = odd ? v2 : x0;
            float go = odd ? v3 : x1;
            if (pixel < PIX) {
                gi += __ldg(&bx1[hc]);
                gf += __ldg(&bx1[64 + hc]);
                gc += __ldg(&bx1[128 + hc]);
                go += __ldg(&bx1[192 + hc]);
                float cold = c1f[pixel * HC1 + hc];
                float w0 = __ldg(&Wc1[hc * PIX + pixel]);
                float w1 = __ldg(&Wc1[10752 + hc * PIX + pixel]);
                float w2 = __ldg(&Wc1[21504 + hc * PIX + pixel]);
                float ci = sigf(gi + cold * w0);
                float cf = sigf(gf + cold * w1);
                float cc = cf * cold + ci * tanhf(gc);
                float co = sigf(go + cc * w2);
                c1f[pixel * HC1 + hc] = cc;
                h1d[pixel * HC1 + hc] = __float2half(co * tanhf(cc));
            }
        }
    }
}

// ---------------- fc1 weight transpose: k follows [pix][ch] flatten ----------------
__global__ void k_wt(const float* __restrict__ fc1_w) {
    int idx = blockIdx.x * blockDim.x + threadIdx.x;
    if (idx >= 10752 * 64) return;
    int k = idx / 64, o = idx % 64;       // k = pix*64 + ch
    int pix = k / 64, ch = k % 64;
    g_fcwT[k * 64 + (o & 31) * 2 + (o >> 5)] = fc1_w[(size_t)o * 10752 + ch * PIX + pix];
}

// ---------------- fc1 head: out[:, 0:64] ----------------
__global__ void k_fc(const float* __restrict__ fc1_b, float* __restrict__ out) {
    __shared__ float shh[8 * 1344];
    int tid = threadIdx.x;
    int b0 = blockIdx.x * 8;
    int it = tid >> 5, o = tid & 31;
    float acc0 = 0.f, acc1 = 0.f;
    const __half* h1f = g_h1[1];          // final h1 (step 6 wrote dst=1)
#pragma unroll 1
    for (int cb = 0; cb < 8; cb++) {
        __syncthreads();
        for (int u = tid; u < 8 * 1344; u += 256) {
            int i2 = u / 1344, kk = u % 1344;
            shh[u] = __half2float(h1f[(size_t)(b0 + i2) * 10752 + cb * 1344 + kk]);
        }
        __syncthreads();
        const float* wp = g_fcwT + (size_t)cb * 1344 * 64 + o * 2;
        const float* hp = shh + it * 1344;
#pragma unroll 4
        for (int kk = 0; kk < 1344; kk++) {
            float hv = hp[kk];
            float2 w2 = __ldg((const float2*)(wp + (size_t)kk * 64));
            acc0 = fmaf(hv, w2.x, acc0);
            acc1 = fmaf(hv, w2.y, acc1);
        }
    }
    out[(size_t)(b0 + it) * 128 + o] = fmaxf(acc0 + fc1_b[o], 0.f);
    out[(size_t)(b0 + it) * 128 + o + 32] = fmaxf(acc1 + fc1_b[o + 32], 0.f);
}

// ---------------- exfc head: out[:, 64:128] ----------------
__global__ void k_exfc(const float* __restrict__ x_ex, const float* __restrict__ w,
                       const float* __restrict__ bias, float* __restrict__ out) {
    int idx = blockIdx.x * blockDim.x + threadIdx.x;
    if (idx >= BATCH * 64) return;
    int b = idx >> 6, o = idx & 63;
    float acc = bias[o];
#pragma unroll
    for (int k = 0; k < 24; k++) acc += x_ex[b * 24 + k] * __ldg(&w[o * 24 + k]);
    out[(size_t)b * 128 + 64 + o] = fmaxf(acc, 0.f);
}

// ---------------- launch ----------------
extern "C" void kernel_launch(void* const* d_in, const int* in_sizes, int n_in,
                              void* d_out, int out_size) {
    const float* input  = (const float*)d_in[0];
    const float* x_ex   = (const float*)d_in[1];
    const float* Wx0    = (const float*)d_in[2];
    const float* bx0    = (const float*)d_in[3];
    const float* Wh0    = (const float*)d_in[4];
    const float* Wc0    = (const float*)d_in[5];
    const float* Wx1    = (const float*)d_in[6];
    const float* bx1    = (const float*)d_in[7];
    const float* Wh1    = (const float*)d_in[8];
    const float* Wc1    = (const float*)d_in[9];
    const float* fc1_w  = (const float*)d_in[10];
    const float* fc1_b  = (const float*)d_in[11];
    const float* exfc_w = (const float*)d_in[12];
    const float* exfc_b = (const float*)d_in[13];
    float* out = (float*)d_out;

    (void)in_sizes; (void)n_in; (void)out_size;

    k_zero<<<4096, 256>>>();
    k_gx0<<<BATCH, 256>>>(input, Wx0, bx0);
    k_wt<<<(10752 * 64 + 255) / 256, 256>>>(fc1_w);
    k_w0h<<<(NCH0 * 16 * 128 + 255) / 256, 256>>>(Wh0);
    k_w1h<<<(NCH1 * 16 * 256 + 255) / 256, 256>>>(Wx1, Wh1);
    k_w0f<<<(NCH0 * 8 * 32 * 4 + 255) / 256, 256>>>();
    k_w1f<<<(NCH1 * 16 * 32 * 4 + 255) / 256, 256>>>();

    for (int s = 0; s < 7; s++) {
        k_cell0tc<<<BATCH, 512>>>(Wc0, s);
        k_cell1tc<<<BATCH, 512>>>(bx1, Wc1, s);
    }

    k_fc<<<BATCH / 8, 256>>>(fc1_b, out);
    k_exfc<<<(BATCH * 64 + 255) / 256, 256>>>(x_ex, exfc_w, exfc_b, out);
}

// round 13
// speedup vs baseline: 5.2395x; 1.3455x over previous
#include <cuda_runtime.h>
#include <cuda_fp16.h>
#include <math.h>

typedef unsigned long long ull;
typedef unsigned int uint;

#define BATCH 2048
#define HGT 7
#define WID 24
#define PIX 168            // 7*24
#define C0IN 2
#define HC0 32
#define HC1 64

// tensor-core geometry
#define P1ROW 26           // padded cols (24 + halo)
#define P1CH 96            // cell1 plane channels (32 h0 + 64 h1)
#define NCH1 54            // cell1: 9 taps * 6 ic16-chunks
#define NCH0 18            // cell0: 9 taps * 2 ic16-chunks

// persistent-kernel SMEM layout (bytes)
#define PL1_BYTES (9*P1ROW*P1CH*2)   // 44928
#define PL0_BYTES (9*P1ROW*HC0*2)    // 14976
#define C0_BYTES  (PIX*33*4)         // 22176 (pad 32->33: bank-conflict-free)
#define C1_BYTES  (PIX*65*4)         // 43680 (pad 64->65)
#define SMEM_TOT  (PL1_BYTES + PL0_BYTES + C0_BYTES + C1_BYTES)   // 125760

// ---------------- scratch ----------------
__device__ float  g_gx0[(size_t)BATCH * PIX * 128];     // [item][pix][hc*4+g], bias included
__device__ __half g_h1out[(size_t)BATCH * PIX * HC1];   // final h1, [item][pix][hc]
__device__ float  g_fcwT[10752 * 64];
__device__ __align__(16) __half g_w0h[NCH0 * 16 * 128]; // staging [chunk][k16][n]
__device__ __align__(16) __half g_w1h[NCH1 * 16 * 256];
// mma B-fragment layouts: [chunk][n8pair][lane][4 x b32]
__device__ __align__(16) uint g_w0f[NCH0 * 8 * 32 * 4];
__device__ __align__(16) uint g_w1f[NCH1 * 16 * 32 * 4];

// ---------------- helpers ----------------
__device__ __forceinline__ float sigf(float x) { return 1.f / (1.f + expf(-x)); }
__device__ __forceinline__ uint smem_u32(const void* p) {
    uint a;
    asm("{ .reg .u64 t; cvta.to.shared.u64 t, %1; cvt.u32.u64 %0, t; }" : "=r"(a) : "l"(p));
    return a;
}

// ---------------- weight transforms (k-major staging layout) ----------------
__global__ void k_w0h(const float* __restrict__ Wh0) {
    int idx = blockIdx.x * blockDim.x + threadIdx.x;
    if (idx >= NCH0 * 16 * 128) return;
    int chunk = idx / 2048, rem = idx % 2048;
    int k = rem / 128, n = rem % 128;
    int tap = chunk >> 1, icc = chunk & 1;
    int ic = icc * 16 + k;
    int hc = n >> 2, g = n & 3;
    g_w0h[idx] = __float2half(Wh0[((g * HC0 + hc) * HC0 + ic) * 9 + tap]);
}

__global__ void k_w1h(const float* __restrict__ Wx1, const float* __restrict__ Wh1) {
    int idx = blockIdx.x * blockDim.x + threadIdx.x;
    if (idx >= NCH1 * 16 * 256) return;
    int chunk = idx / 4096, rem = idx % 4096;
    int k = rem / 256, n = rem % 256;
    int tap = chunk / 6, icc = chunk % 6;
    int ic = icc * 16 + k;
    int hc = n / 4, g = n % 4;
    float v = (ic < HC0) ? Wx1[((g * HC1 + hc) * HC0 + ic) * 9 + tap]
                         : Wh1[((g * HC1 + hc) * HC1 + (ic - HC0)) * 9 + tap];
    g_w1h[idx] = __float2half(v);
}

// ---------------- fragmentizers: k-major -> mma B-fragment order ----------------
__global__ void k_w0f() {
    int idx = blockIdx.x * blockDim.x + threadIdx.x;
    if (idx >= NCH0 * 8 * 32 * 4) return;
    int q = idx & 3, l = (idx >> 2) & 31, pp = (idx >> 7) & 7, c = idx >> 10;
    int tt = pp * 2 + (q >> 1), r = q & 1;
    int k0 = (l & 3) * 2 + r * 8, n = tt * 8 + (l >> 2);
    __half h0 = g_w0h[c * 2048 + k0 * 128 + n];
    __half h1 = g_w0h[c * 2048 + (k0 + 1) * 128 + n];
    ((__half2*)g_w0f)[idx] = __halves2half2(h0, h1);
}

__global__ void k_w1f() {
    int idx = blockIdx.x * blockDim.x + threadIdx.x;
    if (idx >= NCH1 * 16 * 32 * 4) return;
    int q = idx & 3, l = (idx >> 2) & 31, pp = (idx >> 7) & 15, c = idx >> 11;
    int tt = pp * 2 + (q >> 1), r = q & 1;
    int k0 = (l & 3) * 2 + r * 8, n = tt * 8 + (l >> 2);
    __half h0 = g_w1h[c * 4096 + k0 * 256 + n];
    __half h1 = g_w1h[c * 4096 + (k0 + 1) * 256 + n];
    ((__half2*)g_w1f)[idx] = __halves2half2(h0, h1);
}

// ---------------- gx0 = conv(input, Wx0) + bx0, layout [pix][hc*4+g] ----------------
#define SROW0 28
#define SPLANE0 (9*SROW0)
__global__ void k_gx0(const float* __restrict__ input, const float* __restrict__ Wx0,
                      const float* __restrict__ bx0) {
    __shared__ float sin_[C0IN * SPLANE0];
    int b = blockIdx.x, tid = threadIdx.x;
    for (int i = tid; i < C0IN * SPLANE0; i += blockDim.x) sin_[i] = 0.f;
    __syncthreads();
    for (int u = tid; u < C0IN * PIX; u += blockDim.x) {
        int ic = u / PIX, pix = u % PIX, y = pix / WID, x = pix % WID;
        sin_[ic * SPLANE0 + (y + 1) * SROW0 + (x + 1)] = input[(size_t)b * C0IN * PIX + u];
    }
    __syncthreads();
    for (int u = tid; u < 128 * PIX; u += blockDim.x) {
        int oc = u / PIX, pix = u % PIX, y = pix / WID, x = pix % WID;
        float acc = bx0[oc];
#pragma unroll
        for (int ic = 0; ic < C0IN; ic++)
#pragma unroll
            for (int ky = 0; ky < 3; ky++)
#pragma unroll
                for (int kx = 0; kx < 3; kx++)
                    acc += sin_[ic * SPLANE0 + (y + ky) * SROW0 + (x + kx)] *
                           __ldg(&Wx0[oc * 18 + ic * 9 + ky * 3 + kx]);
        int g = oc >> 5, hc = oc & 31;
        g_gx0[(size_t)b * PIX * 128 + pix * 128 + hc * 4 + g] = acc;
    }
}

// ---------------- persistent 7-step dual-layer cell kernel ----------------
__global__ void __launch_bounds__(512, 1)
k_cells(const float* __restrict__ bx1, const float* __restrict__ Wc0,
        const float* __restrict__ Wc1) {
    extern __shared__ __align__(16) char smraw[];
    __half* plane1 = (__half*)smraw;                                  // [9][26][96]
    __half* plane0 = (__half*)(smraw + PL1_BYTES);                    // [9][26][32]
    float*  c0s    = (float*)(smraw + PL1_BYTES + PL0_BYTES);         // [pix][33]
    float*  c1s    = (float*)(smraw + PL1_BYTES + PL0_BYTES + C0_BYTES); // [pix][65]

    int b = blockIdx.x, tid = threadIdx.x;
    int lane = tid & 31, warp = tid >> 5;
    int mg = warp >> 2, ng = warp & 3;

    // ---- zero entire SMEM state (planes incl. halos, c-states) once ----
    uint4 z4; z4.x = z4.y = z4.z = z4.w = 0u;
    for (int i = tid; i < SMEM_TOT / 16; i += 512) ((uint4*)smraw)[i] = z4;
    __syncthreads();

    uint pl1U = smem_u32(plane1);
    uint pl0U = smem_u32(plane0);

    int base26[3];
#pragma unroll
    for (int mt = 0; mt < 3; mt++) {
        int p = (mg * 3 + mt) * 16 + (lane & 15);
        if (p > 167) p = 167;
        base26[mt] = (p / WID + 1) * P1ROW + (p % WID + 1);
    }
    uint ahi = (uint)((lane >> 4) * 16);
    int t = lane & 3, r = lane >> 2, odd = t & 1;

    const float* gx0p = g_gx0 + (size_t)b * PIX * 128;

#pragma unroll 1
    for (int s = 0; s < 7; s++) {
        // ================= Phase A: layer 0 =================
        {
            float d0[3][4][4];
#pragma unroll
            for (int mt = 0; mt < 3; mt++)
#pragma unroll
                for (int j = 0; j < 4; j++)
#pragma unroll
                    for (int q = 0; q < 4; q++) d0[mt][j][q] = 0.f;

#pragma unroll 1
            for (int c = 0; c < NCH0; c++) {
                int tap = c >> 1, icc = c & 1;
                int tapoff = (tap / 3 - 1) * P1ROW + (tap % 3 - 1);
                uint a[3][4];
#pragma unroll
                for (int mt = 0; mt < 3; mt++) {
                    uint aaddr = pl0U + (uint)((base26[mt] + tapoff) * (HC0 * 2)) +
                                 (uint)(icc * 32) + ahi;
                    asm volatile("ldmatrix.sync.aligned.m8n8.x4.shared.b16 {%0,%1,%2,%3}, [%4];"
                                 : "=r"(a[mt][0]), "=r"(a[mt][1]), "=r"(a[mt][2]), "=r"(a[mt][3])
                                 : "r"(aaddr));
                }
                const uint4* fp = (const uint4*)g_w0f + (size_t)(c * 8 + ng * 2) * 32 + lane;
#pragma unroll
                for (int j = 0; j < 2; j++) {
                    uint4 v = __ldg(fp + j * 32);
#pragma unroll
                    for (int mt = 0; mt < 3; mt++) {
                        asm volatile("mma.sync.aligned.m16n8k16.row.col.f32.f16.f16.f32 "
                                     "{%0,%1,%2,%3}, {%4,%5,%6,%7}, {%8,%9}, {%0,%1,%2,%3};"
                                     : "+f"(d0[mt][2 * j][0]), "+f"(d0[mt][2 * j][1]),
                                       "+f"(d0[mt][2 * j][2]), "+f"(d0[mt][2 * j][3])
                                     : "r"(a[mt][0]), "r"(a[mt][1]), "r"(a[mt][2]), "r"(a[mt][3]),
                                       "r"(v.x), "r"(v.y));
                        asm volatile("mma.sync.aligned.m16n8k16.row.col.f32.f16.f16.f32 "
                                     "{%0,%1,%2,%3}, {%4,%5,%6,%7}, {%8,%9}, {%0,%1,%2,%3};"
                                     : "+f"(d0[mt][2 * j + 1][0]), "+f"(d0[mt][2 * j + 1][1]),
                                       "+f"(d0[mt][2 * j + 1][2]), "+f"(d0[mt][2 * j + 1][3])
                                     : "r"(a[mt][0]), "r"(a[mt][1]), "r"(a[mt][2]), "r"(a[mt][3]),
                                       "r"(v.z), "r"(v.w));
                    }
                }
            }
            __syncthreads();   // all reads of plane0 done before in-place h0 update

            // ---- epilogue A: gates -> c0 (SMEM), h0 -> plane0 + plane1 ch0-31 ----
#pragma unroll
            for (int mt = 0; mt < 3; mt++) {
                int tile = mg * 3 + mt;
#pragma unroll
                for (int j = 0; j < 4; j++) {
                    float v0 = d0[mt][j][0], v1 = d0[mt][j][1], v2 = d0[mt][j][2], v3 = d0[mt][j][3];
                    float x0 = __shfl_xor_sync(0xffffffffu, v0, 1);
                    float x1 = __shfl_xor_sync(0xffffffffu, v1, 1);
                    float x2 = __shfl_xor_sync(0xffffffffu, v2, 1);
                    float x3 = __shfl_xor_sync(0xffffffffu, v3, 1);
                    int pixel = tile * 16 + r + odd * 8;
                    int hc = ng * 8 + j * 2 + (t >> 1);
                    float gi = odd ? x2 : v0;
                    float gf = odd ? x3 : v1;
                    float gc = odd ? v2 : x0;
                    float go = odd ? v3 : x1;
                    if (pixel < PIX) {
                        float4 gx = __ldg((const float4*)(gx0p + pixel * 128 + hc * 4));
                        gi += gx.x; gf += gx.y; gc += gx.z; go += gx.w;
                        float cold = c0s[pixel * 33 + hc];
                        float w0 = __ldg(&Wc0[hc * PIX + pixel]);
                        float w1 = __ldg(&Wc0[HC0 * PIX + hc * PIX + pixel]);
                        float w2 = __ldg(&Wc0[2 * HC0 * PIX + hc * PIX + pixel]);
                        float ci = sigf(gi + cold * w0);
                        float cf = sigf(gf + cold * w1);
                        float cc = cf * cold + ci * tanhf(gc);
                        float co = sigf(go + cc * w2);
                        c0s[pixel * 33 + hc] = cc;
                        __half hh = __float2half(co * tanhf(cc));
                        int y = pixel / WID, x = pixel % WID;
                        int cell = (y + 1) * P1ROW + (x + 1);
                        plane0[cell * HC0 + hc] = hh;
                        plane1[cell * P1CH + hc] = hh;
                    }
                }
            }
        }
        __syncthreads();   // h0_new visible in plane1 before phase B reads

        // ================= Phase B: layer 1 =================
        {
            float d1[3][8][4];
#pragma unroll
            for (int mt = 0; mt < 3; mt++)
#pragma unroll
                for (int j = 0; j < 8; j++)
#pragma unroll
                    for (int q = 0; q < 4; q++) d1[mt][j][q] = 0.f;

#pragma unroll 1
            for (int c = 0; c < NCH1; c++) {
                int tap = c / 6, icc = c % 6;
                int tapoff = (tap / 3 - 1) * P1ROW + (tap % 3 - 1);
                uint a[3][4];
#pragma unroll
                for (int mt = 0; mt < 3; mt++) {
                    uint aaddr = pl1U + (uint)((base26[mt] + tapoff) * (P1CH * 2)) +
                                 (uint)(icc * 32) + ahi;
                    asm volatile("ldmatrix.sync.aligned.m8n8.x4.shared.b16 {%0,%1,%2,%3}, [%4];"
                                 : "=r"(a[mt][0]), "=r"(a[mt][1]), "=r"(a[mt][2]), "=r"(a[mt][3])
                                 : "r"(aaddr));
                }
                const uint4* fp = (const uint4*)g_w1f + (size_t)(c * 16 + ng * 4) * 32 + lane;
#pragma unroll
                for (int j = 0; j < 4; j++) {
                    uint4 v = __ldg(fp + j * 32);
#pragma unroll
                    for (int mt = 0; mt < 3; mt++) {
                        asm volatile("mma.sync.aligned.m16n8k16.row.col.f32.f16.f16.f32 "
                                     "{%0,%1,%2,%3}, {%4,%5,%6,%7}, {%8,%9}, {%0,%1,%2,%3};"
                                     : "+f"(d1[mt][2 * j][0]), "+f"(d1[mt][2 * j][1]),
                                       "+f"(d1[mt][2 * j][2]), "+f"(d1[mt][2 * j][3])
                                     : "r"(a[mt][0]), "r"(a[mt][1]), "r"(a[mt][2]), "r"(a[mt][3]),
                                       "r"(v.x), "r"(v.y));
                        asm volatile("mma.sync.aligned.m16n8k16.row.col.f32.f16.f16.f32 "
                                     "{%0,%1,%2,%3}, {%4,%5,%6,%7}, {%8,%9}, {%0,%1,%2,%3};"
                                     : "+f"(d1[mt][2 * j + 1][0]), "+f"(d1[mt][2 * j + 1][1]),
                                       "+f"(d1[mt][2 * j + 1][2]), "+f"(d1[mt][2 * j + 1][3])
                                     : "r"(a[mt][0]), "r"(a[mt][1]), "r"(a[mt][2]), "r"(a[mt][3]),
                                       "r"(v.z), "r"(v.w));
                    }
                }
            }
            __syncthreads();   // all reads of plane1 done before in-place h1 update

            // ---- epilogue B: gates -> c1 (SMEM), h1 -> plane1 ch32-95 (+global at s=6) ----
            __half* h1d = g_h1out + (size_t)b * PIX * HC1;
#pragma unroll
            for (int mt = 0; mt < 3; mt++) {
                int tile = mg * 3 + mt;
#pragma unroll
                for (int j = 0; j < 8; j++) {
                    float v0 = d1[mt][j][0], v1 = d1[mt][j][1], v2 = d1[mt][j][2], v3 = d1[mt][j][3];
                    float x0 = __shfl_xor_sync(0xffffffffu, v0, 1);
                    float x1 = __shfl_xor_sync(0xffffffffu, v1, 1);
                    float x2 = __shfl_xor_sync(0xffffffffu, v2, 1);
                    float x3 = __shfl_xor_sync(0xffffffffu, v3, 1);
                    int pixel = tile * 16 + r + odd * 8;
                    int hc = ng * 16 + j * 2 + (t >> 1);
                    float gi = odd ? x2 : v0;
                    float gf = odd ? x3 : v1;
                    float gc = odd ? v2 : x0;
                    float go = odd ? v3 : x1;
                    if (pixel < PIX) {
                        gi += __ldg(&bx1[hc]);
                        gf += __ldg(&bx1[64 + hc]);
                        gc += __ldg(&bx1[128 + hc]);
                        go += __ldg(&bx1[192 + hc]);
                        float cold = c1s[pixel * 65 + hc];
                        float w0 = __ldg(&Wc1[hc * PIX + pixel]);
                        float w1 = __ldg(&Wc1[10752 + hc * PIX + pixel]);
                        float w2 = __ldg(&Wc1[21504 + hc * PIX + pixel]);
                        float ci = sigf(gi + cold * w0);
                        float cf = sigf(gf + cold * w1);
                        float cc = cf * cold + ci * tanhf(gc);
                        float co = sigf(go + cc * w2);
                        c1s[pixel * 65 + hc] = cc;
                        __half hh = __float2half(co * tanhf(cc));
                        int y = pixel / WID, x = pixel % WID;
                        plane1[((y + 1) * P1ROW + (x + 1)) * P1CH + 32 + hc] = hh;
                        if (s == 6) h1d[pixel * HC1 + hc] = hh;
                    }
                }
            }
        }
        __syncthreads();   // h1_new visible before next step's phase B
    }
}

// ---------------- fc1 weight transpose: k follows [pix][ch] flatten ----------------
__global__ void k_wt(const float* __restrict__ fc1_w) {
    int idx = blockIdx.x * blockDim.x + threadIdx.x;
    if (idx >= 10752 * 64) return;
    int k = idx / 64, o = idx % 64;       // k = pix*64 + ch
    int pix = k / 64, ch = k % 64;
    g_fcwT[k * 64 + (o & 31) * 2 + (o >> 5)] = fc1_w[(size_t)o * 10752 + ch * PIX + pix];
}

// ---------------- fc1 head: out[:, 0:64] ----------------
__global__ void k_fc(const float* __restrict__ fc1_b, float* __restrict__ out) {
    __shared__ float shh[8 * 1344];
    int tid = threadIdx.x;
    int b0 = blockIdx.x * 8;
    int it = tid >> 5, o = tid & 31;
    float acc0 = 0.f, acc1 = 0.f;
    const __half* h1f = g_h1out;
#pragma unroll 1
    for (int cb = 0; cb < 8; cb++) {
        __syncthreads();
        for (int u = tid; u < 8 * 1344; u += 256) {
            int i2 = u / 1344, kk = u % 1344;
            shh[u] = __half2float(h1f[(size_t)(b0 + i2) * 10752 + cb * 1344 + kk]);
        }
        __syncthreads();
        const float* wp = g_fcwT + (size_t)cb * 1344 * 64 + o * 2;
        const float* hp = shh + it * 1344;
#pragma unroll 4
        for (int kk = 0; kk < 1344; kk++) {
            float hv = hp[kk];
            float2 w2 = __ldg((const float2*)(wp + (size_t)kk * 64));
            acc0 = fmaf(hv, w2.x, acc0);
            acc1 = fmaf(hv, w2.y, acc1);
        }
    }
    out[(size_t)(b0 + it) * 128 + o] = fmaxf(acc0 + fc1_b[o], 0.f);
    out[(size_t)(b0 + it) * 128 + o + 32] = fmaxf(acc1 + fc1_b[o + 32], 0.f);
}

// ---------------- exfc head: out[:, 64:128] ----------------
__global__ void k_exfc(const float* __restrict__ x_ex, const float* __restrict__ w,
                       const float* __restrict__ bias, float* __restrict__ out) {
    int idx = blockIdx.x * blockDim.x + threadIdx.x;
    if (idx >= BATCH * 64) return;
    int b = idx >> 6, o = idx & 63;
    float acc = bias[o];
#pragma unroll
    for (int k = 0; k < 24; k++) acc += x_ex[b * 24 + k] * __ldg(&w[o * 24 + k]);
    out[(size_t)b * 128 + 64 + o] = fmaxf(acc, 0.f);
}

// ---------------- launch ----------------
extern "C" void kernel_launch(void* const* d_in, const int* in_sizes, int n_in,
                              void* d_out, int out_size) {
    const float* input  = (const float*)d_in[0];
    const float* x_ex   = (const float*)d_in[1];
    const float* Wx0    = (const float*)d_in[2];
    const float* bx0    = (const float*)d_in[3];
    const float* Wh0    = (const float*)d_in[4];
    const float* Wc0    = (const float*)d_in[5];
    const float* Wx1    = (const float*)d_in[6];
    const float* bx1    = (const float*)d_in[7];
    const float* Wh1    = (const float*)d_in[8];
    const float* Wc1    = (const float*)d_in[9];
    const float* fc1_w  = (const float*)d_in[10];
    const float* fc1_b  = (const float*)d_in[11];
    const float* exfc_w = (const float*)d_in[12];
    const float* exfc_b = (const float*)d_in[13];
    float* out = (float*)d_out;

    (void)in_sizes; (void)n_in; (void)out_size;

    cudaFuncSetAttribute(k_cells, cudaFuncAttributeMaxDynamicSharedMemorySize, SMEM_TOT);

    k_gx0<<<BATCH, 256>>>(input, Wx0, bx0);
    k_wt<<<(10752 * 64 + 255) / 256, 256>>>(fc1_w);
    k_w0h<<<(NCH0 * 16 * 128 + 255) / 256, 256>>>(Wh0);
    k_w1h<<<(NCH1 * 16 * 256 + 255) / 256, 256>>>(Wx1, Wh1);
    k_w0f<<<(NCH0 * 8 * 32 * 4 + 255) / 256, 256>>>();
    k_w1f<<<(NCH1 * 16 * 32 * 4 + 255) / 256, 256>>>();

    k_cells<<<BATCH, 512, SMEM_TOT>>>(bx1, Wc0, Wc1);

    k_fc<<<BATCH / 8, 256>>>(fc1_b, out);
    k_exfc<<<(BATCH * 64 + 255) / 256, 256>>>(x_ex, exfc_w, exfc_b, out);
}